// round 8
// baseline (speedup 1.0000x reference)
#include <cuda_runtime.h>
#include <cstdint>

#define T_LEN 16384
#define BATCH 4
#define HID   128
#define G3    384      // 3*HID gate rows per matrix
#define CLU   8        // CTAs per chain (cluster size)
#define UPC   16       // hidden units per CTA
#define ROWS  96       // 48 W_ih rows + 48 W_hh rows per CTA
#define SEQ_THREADS 384

// ---------------- scratch (static __device__: no allocations allowed) -------
__device__ float g_M[G3 * 4];                          // W_ih @ W_embed  [384,4]
__device__ float g_c[G3];                              // W_ih @ b_embed + b_ih
__device__ float g_gix[(size_t)T_LEN * BATCH * G3];    // precomputed gi for use_x steps (~100MB)
__device__ float g_hs[(size_t)T_LEN * BATCH * HID];    // all hidden states (~32MB)

// ---------------- PTX helpers ----------------------------------------------
__device__ __forceinline__ uint32_t smem_u32(const void* p) {
    uint32_t a;
    asm("{ .reg .u64 t; cvta.to.shared.u64 t, %1; cvt.u32.u64 %0, t; }"
        : "=r"(a) : "l"(p));
    return a;
}
__device__ __forceinline__ uint32_t mapa_u32(uint32_t a, uint32_t rank) {
    uint32_t r;
    asm("mapa.shared::cluster.u32 %0, %1, %2;" : "=r"(r) : "r"(a), "r"(rank));
    return r;
}
__device__ __forceinline__ uint32_t ctarank() {
    uint32_t r; asm("mov.u32 %0, %%cluster_ctarank;" : "=r"(r)); return r;
}
__device__ __forceinline__ void st_remote_f32(uint32_t addr, float v) {
    asm volatile("st.shared::cluster.f32 [%0], %1;" :: "r"(addr), "f"(v) : "memory");
}
__device__ __forceinline__ void mbar_init(uint32_t addr, uint32_t count) {
    asm volatile("mbarrier.init.shared.b64 [%0], %1;" :: "r"(addr), "r"(count) : "memory");
}
__device__ __forceinline__ void mbar_arrive_remote(uint32_t addr) {
    asm volatile("mbarrier.arrive.release.cluster.shared::cluster.b64 _, [%0];"
                 :: "r"(addr) : "memory");
}
__device__ __forceinline__ void mbar_wait(uint32_t mb, uint32_t parity) {
    asm volatile(
        "{\n\t.reg .pred P;\n\t"
        "WLOOP%=:\n\t"
        "mbarrier.try_wait.parity.acquire.cluster.shared::cta.b64 P, [%0], %1, 0x989680;\n\t"
        "@!P bra.uni WLOOP%=;\n\t"
        "}" :: "r"(mb), "r"(parity) : "memory");
}
__device__ __forceinline__ void cluster_sync_all() {
    asm volatile("barrier.cluster.arrive.aligned;" ::: "memory");
    asm volatile("barrier.cluster.wait.aligned;" ::: "memory");
}

__device__ __forceinline__ float sigm(float x) { return 1.0f / (1.0f + expf(-x)); }
__device__ __forceinline__ float eluf(float x) { return x > 0.0f ? x : expm1f(x); }

// ---------------- kernel 0: collapse embed+W_ih into [384,4] ----------------
__global__ void precompute_Mc(const float* __restrict__ W_embed,
                              const float* __restrict__ b_embed,
                              const float* __restrict__ W_ih,
                              const float* __restrict__ b_ih) {
    int j = blockIdx.x * blockDim.x + threadIdx.x;
    if (j >= G3) return;
    float m0 = 0.f, m1 = 0.f, m2 = 0.f, m3 = 0.f, cc = b_ih[j];
    for (int k = 0; k < HID; k++) {
        float w = W_ih[j * HID + k];
        m0 += w * W_embed[k * 4 + 0];
        m1 += w * W_embed[k * 4 + 1];
        m2 += w * W_embed[k * 4 + 2];
        m3 += w * W_embed[k * 4 + 3];
        cc += w * b_embed[k];
    }
    g_M[j * 4 + 0] = m0; g_M[j * 4 + 1] = m1;
    g_M[j * 4 + 2] = m2; g_M[j * 4 + 3] = m3;
    g_c[j] = cc;
}

// ---------------- kernel 1: fill gix ----------------------------------------
// Reference semantics: x = stack([px,py,vx,vy],0).transpose(0,2,1) treats the
// STACKED-TENSOR axis as the model batch and the ORIGINAL batch rows as the
// 4-dim feature vector. So model-batch b's feature vector at time t is
// [tensor_b[0,t], tensor_b[1,t], tensor_b[2,t], tensor_b[3,t]].
// Layout permuted so each seq-CTA reads a contiguous 48-float chunk:
// position p = c*48 + g*16 + u  <->  row j = g*128 + c*16 + u.
__global__ void fill_gix(const float* __restrict__ px, const float* __restrict__ py,
                         const float* __restrict__ vx, const float* __restrict__ vy) {
    size_t idx = (size_t)blockIdx.x * blockDim.x + threadIdx.x;   // one quad of outputs
    const size_t total = (size_t)T_LEN * BATCH * (G3 / 4);
    if (idx >= total) return;
    int p4 = (int)(idx % (G3 / 4));
    size_t tb = idx / (G3 / 4);
    int b = (int)(tb % BATCH);
    int t = (int)(tb / BATCH);
    int p  = p4 * 4;
    int c  = p / 48;
    int pp = p % 48;
    int g  = pp / UPC;
    int u0 = pp % UPC;
    // model-batch b selects the b-th stacked tensor; features = its 4 rows at t
    const float* pb = (b == 0) ? px : (b == 1) ? py : (b == 2) ? vx : vy;
    float x0 = __ldg(pb + 0 * T_LEN + t);
    float x1 = __ldg(pb + 1 * T_LEN + t);
    float x2 = __ldg(pb + 2 * T_LEN + t);
    float x3 = __ldg(pb + 3 * T_LEN + t);
    float r[4];
#pragma unroll
    for (int q = 0; q < 4; q++) {
        int j = g * HID + c * UPC + u0 + q;
        r[q] = g_c[j] + g_M[j * 4 + 0] * x0 + g_M[j * 4 + 1] * x1
                      + g_M[j * 4 + 2] * x2 + g_M[j * 4 + 3] * x3;
    }
    float4* dst = reinterpret_cast<float4*>(&g_gix[tb * G3 + p]);
    *dst = make_float4(r[0], r[1], r[2], r[3]);
}

// ---------------- kernel 2: the sequential GRU scan -------------------------
// 4 clusters of 8 CTAs (one cluster per batch chain). CTA c owns hidden units
// [c*16, c*16+16). 384 threads: thread = row*4 + quarter; 96 rows =
// 48 W_ih rows (gate*16+u) then 48 W_hh rows. Weights live in registers.
__global__ void __cluster_dims__(CLU, 1, 1) __launch_bounds__(SEQ_THREADS, 1)
gru_scan(const float* __restrict__ W_ih, const float* __restrict__ W_hh,
         const float* __restrict__ b_ih, const float* __restrict__ b_hh,
         const int* __restrict__ step_mask, const int* __restrict__ ctx_ptr) {
    __shared__ __align__(16) float h_buf[2][HID];
    __shared__ float rowsum[ROWS];
    __shared__ __align__(8) unsigned long long mbar_storage;

    const int tid = threadIdx.x;
    const int c = (int)ctarank();
    const int b = blockIdx.x / CLU;
    const int r = tid >> 2;          // row 0..95
    const int q = tid & 3;           // quarter 0..3 (32 k's each)
    const int rot = ((q << 1) | (r & 1)) & 7;   // bank-conflict-free rotation

    // weight rows -> registers
    const int rl   = (r < 48) ? r : (r - 48);
    const int gate = rl / UPC;
    const int u_r  = rl % UPC;
    const int j    = gate * HID + c * UPC + u_r;
    const float* Wsrc = ((r < 48) ? W_ih : W_hh) + (size_t)j * HID + q * 32;
    const float4* Wsrc4 = reinterpret_cast<const float4*>(Wsrc);
    float4 w[8];
#pragma unroll
    for (int s = 0; s < 8; s++) w[s] = __ldg(&Wsrc4[(s + rot) & 7]);

    // init
    if (tid < HID) { h_buf[0][tid] = 0.0f; h_buf[1][tid] = 0.0f; }
    const uint32_t mb_local = smem_u32(&mbar_storage);
    if (tid == 0) mbar_init(mb_local, UPC * CLU);   // 128 arrivals per step
    __syncthreads();
    cluster_sync_all();   // peers' mbarriers + zeroed h visible before any remote op

    int ctx = ctx_ptr[0];
    if (ctx < 1) ctx = 1;

    const bool unit_thread = (tid < UPC);
    const int u = tid;             // valid only for unit threads

    // biases for unit threads
    float bihr = 0.f, bihz = 0.f, bihn = 0.f, bhhr = 0.f, bhhz = 0.f, bhhn = 0.f;
    if (unit_thread) {
        int gj = c * UPC + u;
        bihr = b_ih[gj]; bihz = b_ih[HID + gj]; bihn = b_ih[2 * HID + gj];
        bhhr = b_hh[gj]; bhhz = b_hh[HID + gj]; bhhn = b_hh[2 * HID + gj];
    }

    // precomputed remote addresses for this unit's h slot (both buffers, 8 peers)
    uint32_t h_remote[2][CLU];
    uint32_t mb_remote[CLU];
    if (unit_thread) {
        uint32_t a0 = smem_u32(&h_buf[0][c * UPC + u]);
        uint32_t a1 = smem_u32(&h_buf[1][c * UPC + u]);
#pragma unroll
        for (int p = 0; p < CLU; p++) {
            h_remote[0][p] = mapa_u32(a0, p);
            h_remote[1][p] = mapa_u32(a1, p);
            mb_remote[p]   = mapa_u32(mb_local, p);
        }
    }

    // prefetch gix + mask for t=0
    float gnr = 0.f, gnz = 0.f, gnn = 0.f; int nmask = 0;
    if (unit_thread) {
        const float* gp = g_gix + ((size_t)0 * BATCH + b) * G3 + c * 48 + u;
        gnr = __ldg(gp); gnz = __ldg(gp + UPC); gnn = __ldg(gp + 2 * UPC);
        nmask = __ldg(step_mask + 0);
    }

    for (int t = 0; t < T_LEN; t++) {
        float gcr = gnr, gcz = gnz, gcn = gnn; int cmask = nmask;
        if (unit_thread && (t + 1 < T_LEN)) {
            const float* gp = g_gix + ((size_t)(t + 1) * BATCH + b) * G3 + c * 48 + u;
            gnr = __ldg(gp); gnz = __ldg(gp + UPC); gnn = __ldg(gp + 2 * UPC);
            nmask = __ldg(step_mask + t + 1);
        }

        // ---- dot products: this thread's 32-wide slice of its row ----
        const float4* hb4 = reinterpret_cast<const float4*>(&h_buf[t & 1][q * 32]);
        float acc = 0.0f;
#pragma unroll
        for (int s = 0; s < 8; s++) {
            float4 h4 = hb4[(s + rot) & 7];
            acc += w[s].x * h4.x + w[s].y * h4.y + w[s].z * h4.z + w[s].w * h4.w;
        }
        acc += __shfl_xor_sync(0xffffffffu, acc, 1);
        acc += __shfl_xor_sync(0xffffffffu, acc, 2);
        if (q == 0) rowsum[r] = acc;
        __syncthreads();

        // ---- gate math + broadcast (16 unit threads) ----
        if (unit_thread) {
            float gihr = rowsum[u]            + bihr;
            float gihz = rowsum[UPC + u]      + bihz;
            float gihn = rowsum[2 * UPC + u]  + bihn;
            float ghr  = rowsum[48 + u]           + bhhr;
            float ghz  = rowsum[48 + UPC + u]     + bhhz;
            float ghn  = rowsum[48 + 2 * UPC + u] + bhhn;
            bool ux = (t < ctx) || (cmask == 0);
            float gr = ux ? gcr : gihr;
            float gz = ux ? gcz : gihz;
            float gn = ux ? gcn : gihn;
            float rr = sigm(gr + ghr);
            float zz = sigm(gz + ghz);
            float nn = tanhf(gn + rr * ghn);
            float hold = h_buf[t & 1][c * UPC + u];
            float hnew = (1.0f - zz) * nn + zz * hold;
            g_hs[((size_t)t * BATCH + b) * HID + c * UPC + u] = hnew;
            const int nb = (t + 1) & 1;
#pragma unroll
            for (int pp = 0; pp < CLU; pp++) {
                int p = (c + pp) & (CLU - 1);
                st_remote_f32(h_remote[nb][p], hnew);
            }
#pragma unroll
            for (int pp = 0; pp < CLU; pp++) {
                int p = (c + pp) & (CLU - 1);
                mbar_arrive_remote(mb_remote[p]);
            }
        }
        mbar_wait(mb_local, (uint32_t)(t & 1));
    }
}

// ---------------- kernel 3: MLP head ----------------------------------------
__global__ void __launch_bounds__(256) mlp_head(
    const float* __restrict__ W1, const float* __restrict__ b1,
    const float* __restrict__ W2, const float* __restrict__ b2,
    const float* __restrict__ W3, const float* __restrict__ b3,
    float* __restrict__ out) {
    __shared__ float W1s[HID][64];    // transposed: W1s[k][i] = W1[i][k]
    __shared__ float W3s[2][64];
    __shared__ float b1s[64], b2s[64], b3s[2];
    __shared__ float hrow[4][HID];
    __shared__ float y1s[4][64];
    __shared__ float y2s[4][64];

    const int tid = threadIdx.x;
    for (int idx = tid; idx < 64 * HID; idx += 256) {
        int i = idx / HID, k = idx % HID;
        W1s[k][i] = W1[idx];
    }
    if (tid < 128) W3s[tid >> 6][tid & 63] = W3[tid];
    if (tid < 64)  b1s[tid] = b1[tid];
    if (tid < 64)  b2s[tid] = b2[tid];
    if (tid < 2)   b3s[tid] = b3[tid];
    // W2 row (transposed access) into registers: thread with lane i needs W2[i][k]
    const int g = tid >> 6, i = tid & 63;
    float w2r[64];
#pragma unroll
    for (int k = 0; k < 64; k++) w2r[k] = __ldg(&W2[i * 64 + k]);
    __syncthreads();

    const int total_rows = T_LEN * BATCH;
    for (int m0 = blockIdx.x * 4; m0 < total_rows; m0 += gridDim.x * 4) {
        for (int x = tid; x < 4 * HID; x += 256)
            hrow[x >> 7][x & 127] = g_hs[(size_t)m0 * HID + x];
        __syncthreads();

        float a = b1s[i];
#pragma unroll 16
        for (int k = 0; k < HID; k++) a += W1s[k][i] * hrow[g][k];
        y1s[g][i] = eluf(a);
        __syncthreads();

        float o = b2s[i];
#pragma unroll
        for (int k = 0; k < 64; k++) o += w2r[k] * y1s[g][k];
        y2s[g][i] = eluf(o);
        __syncthreads();

        if (tid < 8) {
            int gg = tid >> 1, oo = tid & 1;
            int m = m0 + gg;
            float s = b3s[oo];
#pragma unroll
            for (int k = 0; k < 64; k++) s += W3s[oo][k] * y2s[gg][k];
            int t = m >> 2, bb = m & 3;
            out[(size_t)oo * total_rows + (size_t)bb * T_LEN + t] = s;
        }
        __syncthreads();
    }
}

// ---------------- launch -----------------------------------------------------
extern "C" void kernel_launch(void* const* d_in, const int* in_sizes, int n_in,
                              void* d_out, int out_size) {
    const float* px      = (const float*)d_in[0];
    const float* py      = (const float*)d_in[1];
    const float* vx      = (const float*)d_in[2];
    const float* vy      = (const float*)d_in[3];
    const float* W_embed = (const float*)d_in[4];
    const float* b_embed = (const float*)d_in[5];
    const float* W_ih    = (const float*)d_in[6];
    const float* W_hh    = (const float*)d_in[7];
    const float* b_ih    = (const float*)d_in[8];
    const float* b_hh    = (const float*)d_in[9];
    const float* W1      = (const float*)d_in[10];
    const float* b1      = (const float*)d_in[11];
    const float* W2      = (const float*)d_in[12];
    const float* b2      = (const float*)d_in[13];
    const float* W3      = (const float*)d_in[14];
    const float* b3      = (const float*)d_in[15];
    const int*   smask   = (const int*)d_in[16];
    const int*   ctx     = (const int*)d_in[17];

    precompute_Mc<<<1, G3>>>(W_embed, b_embed, W_ih, b_ih);

    const size_t quads = (size_t)T_LEN * BATCH * (G3 / 4);
    fill_gix<<<(unsigned)((quads + 255) / 256), 256>>>(px, py, vx, vy);

    gru_scan<<<BATCH * CLU, SEQ_THREADS>>>(W_ih, W_hh, b_ih, b_hh, smask, ctx);

    mlp_head<<<512, 256>>>(W1, b1, W2, b2, W3, b3, (float*)d_out);
}

// round 10
// speedup vs baseline: 1.4268x; 1.4268x over previous
#include <cuda_runtime.h>
#include <cstdint>

#define T_LEN 16384
#define BATCH 4
#define HID   128
#define G3    384      // 3*HID gate rows per matrix
#define CLU   8        // CTAs per chain (cluster size)
#define UPC   16       // hidden units per CTA
#define ROWS  96       // 48 W_ih rows + 48 W_hh rows per CTA
#define SEQ_THREADS 384

// ---------------- scratch (static __device__: no allocations allowed) -------
__device__ float g_M[G3 * 4];                          // W_ih @ W_embed  [384,4]
__device__ float g_c[G3];                              // W_ih @ b_embed + b_ih
__device__ float g_gix[(size_t)T_LEN * BATCH * G3];    // precomputed gi for use_x steps
__device__ float g_hs[(size_t)T_LEN * BATCH * HID];    // all hidden states

// ---------------- PTX helpers ----------------------------------------------
__device__ __forceinline__ uint32_t smem_u32(const void* p) {
    uint32_t a;
    asm("{ .reg .u64 t; cvta.to.shared.u64 t, %1; cvt.u32.u64 %0, t; }"
        : "=r"(a) : "l"(p));
    return a;
}
__device__ __forceinline__ uint32_t mapa_u32(uint32_t a, uint32_t rank) {
    uint32_t r;
    asm("mapa.shared::cluster.u32 %0, %1, %2;" : "=r"(r) : "r"(a), "r"(rank));
    return r;
}
__device__ __forceinline__ uint32_t ctarank() {
    uint32_t r; asm("mov.u32 %0, %%cluster_ctarank;" : "=r"(r)); return r;
}
__device__ __forceinline__ void st_remote_f32(uint32_t addr, float v) {
    asm volatile("st.shared::cluster.f32 [%0], %1;" :: "r"(addr), "f"(v) : "memory");
}
__device__ __forceinline__ void mbar_init(uint32_t addr, uint32_t count) {
    asm volatile("mbarrier.init.shared.b64 [%0], %1;" :: "r"(addr), "r"(count) : "memory");
}
__device__ __forceinline__ void fence_acqrel_cluster() {
    asm volatile("fence.acq_rel.cluster;" ::: "memory");
}
__device__ __forceinline__ void mbar_arrive_relaxed_remote(uint32_t addr) {
    asm volatile("mbarrier.arrive.relaxed.cluster.shared::cluster.b64 _, [%0];"
                 :: "r"(addr) : "memory");
}
__device__ __forceinline__ void mbar_wait(uint32_t mb, uint32_t parity) {
    asm volatile(
        "{\n\t.reg .pred P;\n\t"
        "WLOOP%=:\n\t"
        "mbarrier.try_wait.parity.acquire.cluster.shared::cta.b64 P, [%0], %1, 0x989680;\n\t"
        "@!P bra.uni WLOOP%=;\n\t"
        "}" :: "r"(mb), "r"(parity) : "memory");
}
__device__ __forceinline__ void cluster_sync_all() {
    asm volatile("barrier.cluster.arrive.aligned;" ::: "memory");
    asm volatile("barrier.cluster.wait.aligned;" ::: "memory");
}

__device__ __forceinline__ float sigm_fast(float x) {
    return __fdividef(1.0f, 1.0f + __expf(-x));
}
__device__ __forceinline__ float tanh_fast(float x) {
    float xc = fminf(fmaxf(x, -15.0f), 15.0f);
    float e  = __expf(-2.0f * xc);
    return __fdividef(1.0f - e, 1.0f + e);
}
__device__ __forceinline__ float eluf(float x) { return x > 0.0f ? x : expm1f(x); }

// ---------------- kernel 0: collapse embed+W_ih into [384,4] ----------------
__global__ void precompute_Mc(const float* __restrict__ W_embed,
                              const float* __restrict__ b_embed,
                              const float* __restrict__ W_ih,
                              const float* __restrict__ b_ih) {
    int j = blockIdx.x * blockDim.x + threadIdx.x;
    if (j >= G3) return;
    float m0 = 0.f, m1 = 0.f, m2 = 0.f, m3 = 0.f, cc = b_ih[j];
    for (int k = 0; k < HID; k++) {
        float w = W_ih[j * HID + k];
        m0 += w * W_embed[k * 4 + 0];
        m1 += w * W_embed[k * 4 + 1];
        m2 += w * W_embed[k * 4 + 2];
        m3 += w * W_embed[k * 4 + 3];
        cc += w * b_embed[k];
    }
    g_M[j * 4 + 0] = m0; g_M[j * 4 + 1] = m1;
    g_M[j * 4 + 2] = m2; g_M[j * 4 + 3] = m3;
    g_c[j] = cc;
}

// ---------------- kernel 1: fill gix ----------------------------------------
// Reference: x = stack([px,py,vx,vy],0).transpose(0,2,1) — stacked-tensor axis
// is the model batch; original batch rows are the 4-dim feature vector.
__global__ void fill_gix(const float* __restrict__ px, const float* __restrict__ py,
                         const float* __restrict__ vx, const float* __restrict__ vy) {
    size_t idx = (size_t)blockIdx.x * blockDim.x + threadIdx.x;   // one quad
    const size_t total = (size_t)T_LEN * BATCH * (G3 / 4);
    if (idx >= total) return;
    int p4 = (int)(idx % (G3 / 4));
    size_t tb = idx / (G3 / 4);
    int b = (int)(tb % BATCH);
    int t = (int)(tb / BATCH);
    int p  = p4 * 4;
    int c  = p / 48;
    int pp = p % 48;
    int g  = pp / UPC;
    int u0 = pp % UPC;
    const float* pb = (b == 0) ? px : (b == 1) ? py : (b == 2) ? vx : vy;
    float x0 = __ldg(pb + 0 * T_LEN + t);
    float x1 = __ldg(pb + 1 * T_LEN + t);
    float x2 = __ldg(pb + 2 * T_LEN + t);
    float x3 = __ldg(pb + 3 * T_LEN + t);
    float r[4];
#pragma unroll
    for (int q = 0; q < 4; q++) {
        int j = g * HID + c * UPC + u0 + q;
        r[q] = g_c[j] + g_M[j * 4 + 0] * x0 + g_M[j * 4 + 1] * x1
                      + g_M[j * 4 + 2] * x2 + g_M[j * 4 + 3] * x3;
    }
    float4* dst = reinterpret_cast<float4*>(&g_gix[tb * G3 + p]);
    *dst = make_float4(r[0], r[1], r[2], r[3]);
}

// ---------------- kernel 2: the sequential GRU scan -------------------------
// 4 clusters of 8 CTAs (one per batch chain). CTA c owns hidden units
// [c*16, c*16+16). Gate math is REPLICATED across warps 0-7 (lanes 0-15);
// warp w stores the CTA's 16 new h values to peer w only and issues ONE
// fence+arrive — 8 arrivals per mbarrier per step (was 128).
__global__ void __cluster_dims__(CLU, 1, 1) __launch_bounds__(SEQ_THREADS, 1)
gru_scan(const float* __restrict__ W_ih, const float* __restrict__ W_hh,
         const float* __restrict__ b_ih, const float* __restrict__ b_hh,
         const int* __restrict__ step_mask, const int* __restrict__ ctx_ptr) {
    __shared__ __align__(16) float h_buf[2][HID];
    __shared__ float rowsum[2][ROWS];
    __shared__ __align__(8) unsigned long long mbar_storage;

    const int tid  = threadIdx.x;
    const int c    = (int)ctarank();
    const int b    = blockIdx.x / CLU;
    const int r    = tid >> 2;       // row 0..95
    const int q    = tid & 3;        // quarter 0..3 (32 k's each)
    const int wid  = tid >> 5;       // warp 0..11
    const int lane = tid & 31;
    const int rot  = ((q << 1) | (r & 1)) & 7;   // bank-conflict-free rotation

    // weight rows -> registers
    const int rl   = (r < 48) ? r : (r - 48);
    const int gate = rl / UPC;
    const int u_r  = rl % UPC;
    const int j    = gate * HID + c * UPC + u_r;
    const float* Wsrc = ((r < 48) ? W_ih : W_hh) + (size_t)j * HID + q * 32;
    const float4* Wsrc4 = reinterpret_cast<const float4*>(Wsrc);
    float4 w[8];
#pragma unroll
    for (int s = 0; s < 8; s++) w[s] = __ldg(&Wsrc4[(s + rot) & 7]);

    // init
    if (tid < HID) { h_buf[0][tid] = 0.0f; h_buf[1][tid] = 0.0f; }
    const uint32_t mb_local = smem_u32(&mbar_storage);
    if (tid == 0) mbar_init(mb_local, CLU);   // 8 arrivals per step
    __syncthreads();
    cluster_sync_all();   // peers' mbarriers + zeroed h visible before any remote op

    int ctx = ctx_ptr[0];
    if (ctx < 1) ctx = 1;

    const bool peer_warp   = (wid < CLU);               // warps 0..7
    const bool gate_thread = peer_warp && (lane < UPC); // lanes 0..15 of those
    const int  u = lane;                                 // unit (gate threads)

    // biases (replicated across the 8 gate warps)
    float bihr = 0.f, bihz = 0.f, bihn = 0.f, bhhr = 0.f, bhhz = 0.f, bhhn = 0.f;
    if (gate_thread) {
        int gj = c * UPC + u;
        bihr = b_ih[gj]; bihz = b_ih[HID + gj]; bihn = b_ih[2 * HID + gj];
        bhhr = b_hh[gj]; bhhz = b_hh[HID + gj]; bhhn = b_hh[2 * HID + gj];
    }

    // remote addresses: warp w -> peer w; lane u's slot in both buffers
    uint32_t h_rem0 = 0, h_rem1 = 0, mb_rem = 0;
    if (gate_thread) {
        h_rem0 = mapa_u32(smem_u32(&h_buf[0][c * UPC + u]), (uint32_t)wid);
        h_rem1 = mapa_u32(smem_u32(&h_buf[1][c * UPC + u]), (uint32_t)wid);
    }
    if (peer_warp && lane == 0) mb_rem = mapa_u32(mb_local, (uint32_t)wid);

    // prefetch gix + mask for t=0 (replicated loads hit L1-broadcast)
    float gnr = 0.f, gnz = 0.f, gnn = 0.f; int nmask = 0;
    if (gate_thread) {
        const float* gp = g_gix + ((size_t)0 * BATCH + b) * G3 + c * 48 + u;
        gnr = __ldg(gp); gnz = __ldg(gp + UPC); gnn = __ldg(gp + 2 * UPC);
        nmask = __ldg(step_mask + 0);
    }

    for (int t = 0; t < T_LEN; t++) {
        const int cur = t & 1;
        float gcr = gnr, gcz = gnz, gcn = gnn; int cmask = nmask;
        if (gate_thread && (t + 1 < T_LEN)) {
            const float* gp = g_gix + ((size_t)(t + 1) * BATCH + b) * G3 + c * 48 + u;
            gnr = __ldg(gp); gnz = __ldg(gp + UPC); gnn = __ldg(gp + 2 * UPC);
            nmask = __ldg(step_mask + t + 1);
        }

        // ---- dot products: this thread's 32-wide slice of its row ----
        const float4* hb4 = reinterpret_cast<const float4*>(&h_buf[cur][q * 32]);
        float acc = 0.0f;
#pragma unroll
        for (int s = 0; s < 8; s++) {
            float4 h4 = hb4[(s + rot) & 7];
            acc += w[s].x * h4.x + w[s].y * h4.y + w[s].z * h4.z + w[s].w * h4.w;
        }
        acc += __shfl_xor_sync(0xffffffffu, acc, 1);
        acc += __shfl_xor_sync(0xffffffffu, acc, 2);
        if (q == 0) rowsum[cur][r] = acc;
        __syncthreads();

        // ---- replicated gate math + per-warp peer store ----
        if (gate_thread) {
            float gihr = rowsum[cur][u]            + bihr;
            float gihz = rowsum[cur][UPC + u]      + bihz;
            float gihn = rowsum[cur][2 * UPC + u]  + bihn;
            float ghr  = rowsum[cur][48 + u]           + bhhr;
            float ghz  = rowsum[cur][48 + UPC + u]     + bhhz;
            float ghn  = rowsum[cur][48 + 2 * UPC + u] + bhhn;
            bool ux = (t < ctx) || (cmask == 0);
            float gr = ux ? gcr : gihr;
            float gz = ux ? gcz : gihz;
            float gn = ux ? gcn : gihn;
            float rr = sigm_fast(gr + ghr);
            float zz = sigm_fast(gz + ghz);
            float nn = tanh_fast(gn + rr * ghn);
            float hold = h_buf[cur][c * UPC + u];
            float hnew = (1.0f - zz) * nn + zz * hold;
            if (wid == 0)
                g_hs[((size_t)t * BATCH + b) * HID + c * UPC + u] = hnew;
            st_remote_f32((cur == 0) ? h_rem1 : h_rem0, hnew);  // buffer (t+1)&1
        }
        if (peer_warp) {
            __syncwarp();                       // lanes' stores ordered before fence
            if (lane == 0) {
                fence_acqrel_cluster();         // elevate to cluster scope
                mbar_arrive_relaxed_remote(mb_rem);
            }
        }
        mbar_wait(mb_local, (uint32_t)cur);
    }
}

// ---------------- kernel 3: MLP head ----------------------------------------
__global__ void __launch_bounds__(256) mlp_head(
    const float* __restrict__ W1, const float* __restrict__ b1,
    const float* __restrict__ W2, const float* __restrict__ b2,
    const float* __restrict__ W3, const float* __restrict__ b3,
    float* __restrict__ out) {
    __shared__ float W1s[HID][64];    // transposed: W1s[k][i] = W1[i][k]
    __shared__ float W3s[2][64];
    __shared__ float b1s[64], b2s[64], b3s[2];
    __shared__ float hrow[4][HID];
    __shared__ float y1s[4][64];
    __shared__ float y2s[4][64];

    const int tid = threadIdx.x;
    for (int idx = tid; idx < 64 * HID; idx += 256) {
        int i = idx / HID, k = idx % HID;
        W1s[k][i] = W1[idx];
    }
    if (tid < 128) W3s[tid >> 6][tid & 63] = W3[tid];
    if (tid < 64)  b1s[tid] = b1[tid];
    if (tid < 64)  b2s[tid] = b2[tid];
    if (tid < 2)   b3s[tid] = b3[tid];
    const int g = tid >> 6, i = tid & 63;
    float w2r[64];
#pragma unroll
    for (int k = 0; k < 64; k++) w2r[k] = __ldg(&W2[i * 64 + k]);
    __syncthreads();

    const int total_rows = T_LEN * BATCH;
    for (int m0 = blockIdx.x * 4; m0 < total_rows; m0 += gridDim.x * 4) {
        for (int x = tid; x < 4 * HID; x += 256)
            hrow[x >> 7][x & 127] = g_hs[(size_t)m0 * HID + x];
        __syncthreads();

        float a = b1s[i];
#pragma unroll 16
        for (int k = 0; k < HID; k++) a += W1s[k][i] * hrow[g][k];
        y1s[g][i] = eluf(a);
        __syncthreads();

        float o = b2s[i];
#pragma unroll
        for (int k = 0; k < 64; k++) o += w2r[k] * y1s[g][k];
        y2s[g][i] = eluf(o);
        __syncthreads();

        if (tid < 8) {
            int gg = tid >> 1, oo = tid & 1;
            int m = m0 + gg;
            float s = b3s[oo];
#pragma unroll
            for (int k = 0; k < 64; k++) s += W3s[oo][k] * y2s[gg][k];
            int t = m >> 2, bb = m & 3;
            out[(size_t)oo * total_rows + (size_t)bb * T_LEN + t] = s;
        }
        __syncthreads();
    }
}

// ---------------- launch -----------------------------------------------------
extern "C" void kernel_launch(void* const* d_in, const int* in_sizes, int n_in,
                              void* d_out, int out_size) {
    const float* px      = (const float*)d_in[0];
    const float* py      = (const float*)d_in[1];
    const float* vx      = (const float*)d_in[2];
    const float* vy      = (const float*)d_in[3];
    const float* W_embed = (const float*)d_in[4];
    const float* b_embed = (const float*)d_in[5];
    const float* W_ih    = (const float*)d_in[6];
    const float* W_hh    = (const float*)d_in[7];
    const float* b_ih    = (const float*)d_in[8];
    const float* b_hh    = (const float*)d_in[9];
    const float* W1      = (const float*)d_in[10];
    const float* b1      = (const float*)d_in[11];
    const float* W2      = (const float*)d_in[12];
    const float* b2      = (const float*)d_in[13];
    const float* W3      = (const float*)d_in[14];
    const float* b3      = (const float*)d_in[15];
    const int*   smask   = (const int*)d_in[16];
    const int*   ctx     = (const int*)d_in[17];

    precompute_Mc<<<1, G3>>>(W_embed, b_embed, W_ih, b_ih);

    const size_t quads = (size_t)T_LEN * BATCH * (G3 / 4);
    fill_gix<<<(unsigned)((quads + 255) / 256), 256>>>(px, py, vx, vy);

    gru_scan<<<BATCH * CLU, SEQ_THREADS>>>(W_ih, W_hh, b_ih, b_hh, smask, ctx);

    mlp_head<<<512, 256>>>(W1, b1, W2, b2, W3, b3, (float*)d_out);
}

// round 11
// speedup vs baseline: 3.4967x; 2.4506x over previous
#include <cuda_runtime.h>
#include <cstdint>

#define T_LEN 16384
#define BATCH 4
#define HID   128
#define G3    384      // 3*HID gate rows per matrix
#define CLU   8        // CTAs per chain (cluster size)
#define UPC   16       // hidden units per CTA
#define ROWS  96       // 48 W_ih rows + 48 W_hh rows per CTA
#define SEQ_THREADS 384
#define STEP_TX (CLU * UPC * 4)   // 512 bytes of h per step per CTA barrier

// ---------------- scratch (static __device__: no allocations allowed) -------
__device__ float g_M[G3 * 4];                          // W_ih @ W_embed  [384,4]
__device__ float g_c[G3];                              // W_ih @ b_embed + b_ih
__device__ float g_gix[(size_t)T_LEN * BATCH * G3];    // precomputed gi for use_x steps
__device__ float g_hs[(size_t)T_LEN * BATCH * HID];    // all hidden states

// ---------------- PTX helpers ----------------------------------------------
__device__ __forceinline__ uint32_t smem_u32(const void* p) {
    uint32_t a;
    asm("{ .reg .u64 t; cvta.to.shared.u64 t, %1; cvt.u32.u64 %0, t; }"
        : "=r"(a) : "l"(p));
    return a;
}
__device__ __forceinline__ uint32_t mapa_u32(uint32_t a, uint32_t rank) {
    uint32_t r;
    asm("mapa.shared::cluster.u32 %0, %1, %2;" : "=r"(r) : "r"(a), "r"(rank));
    return r;
}
__device__ __forceinline__ uint32_t ctarank() {
    uint32_t r; asm("mov.u32 %0, %%cluster_ctarank;" : "=r"(r)); return r;
}
// fused data store + tx-completion on the peer's mbarrier (sm_90+)
__device__ __forceinline__ void st_async_f32(uint32_t addr, float v, uint32_t mbar) {
    asm volatile(
        "st.async.shared::cluster.mbarrier::complete_tx::bytes.f32 [%0], %1, [%2];"
        :: "r"(addr), "f"(v), "r"(mbar) : "memory");
}
__device__ __forceinline__ void mbar_init(uint32_t addr, uint32_t count) {
    asm volatile("mbarrier.init.shared.b64 [%0], %1;" :: "r"(addr), "r"(count) : "memory");
}
__device__ __forceinline__ void mbar_expect_tx(uint32_t addr, uint32_t bytes) {
    asm volatile("mbarrier.arrive.expect_tx.shared.b64 _, [%0], %1;"
                 :: "r"(addr), "r"(bytes) : "memory");
}
__device__ __forceinline__ void mbar_wait(uint32_t mb, uint32_t parity) {
    asm volatile(
        "{\n\t.reg .pred P;\n\t"
        "WLOOP%=:\n\t"
        "mbarrier.try_wait.parity.acquire.cluster.shared::cta.b64 P, [%0], %1, 0x989680;\n\t"
        "@!P bra.uni WLOOP%=;\n\t"
        "}" :: "r"(mb), "r"(parity) : "memory");
}
__device__ __forceinline__ void cluster_sync_all() {
    asm volatile("barrier.cluster.arrive.aligned;" ::: "memory");
    asm volatile("barrier.cluster.wait.aligned;" ::: "memory");
}

__device__ __forceinline__ float sigm_fast(float x) {
    return __fdividef(1.0f, 1.0f + __expf(-x));
}
__device__ __forceinline__ float tanh_fast(float x) {
    float xc = fminf(fmaxf(x, -15.0f), 15.0f);
    float e  = __expf(-2.0f * xc);
    return __fdividef(1.0f - e, 1.0f + e);
}
__device__ __forceinline__ float eluf(float x) { return x > 0.0f ? x : expm1f(x); }

// ---------------- kernel 0: collapse embed+W_ih into [384,4] ----------------
__global__ void precompute_Mc(const float* __restrict__ W_embed,
                              const float* __restrict__ b_embed,
                              const float* __restrict__ W_ih,
                              const float* __restrict__ b_ih) {
    int j = blockIdx.x * blockDim.x + threadIdx.x;
    if (j >= G3) return;
    float m0 = 0.f, m1 = 0.f, m2 = 0.f, m3 = 0.f, cc = b_ih[j];
    for (int k = 0; k < HID; k++) {
        float w = W_ih[j * HID + k];
        m0 += w * W_embed[k * 4 + 0];
        m1 += w * W_embed[k * 4 + 1];
        m2 += w * W_embed[k * 4 + 2];
        m3 += w * W_embed[k * 4 + 3];
        cc += w * b_embed[k];
    }
    g_M[j * 4 + 0] = m0; g_M[j * 4 + 1] = m1;
    g_M[j * 4 + 2] = m2; g_M[j * 4 + 3] = m3;
    g_c[j] = cc;
}

// ---------------- kernel 1: fill gix ----------------------------------------
// Reference: x = stack([px,py,vx,vy],0).transpose(0,2,1) — stacked-tensor axis
// is the model batch; original batch rows are the 4-dim feature vector.
__global__ void fill_gix(const float* __restrict__ px, const float* __restrict__ py,
                         const float* __restrict__ vx, const float* __restrict__ vy) {
    size_t idx = (size_t)blockIdx.x * blockDim.x + threadIdx.x;   // one quad
    const size_t total = (size_t)T_LEN * BATCH * (G3 / 4);
    if (idx >= total) return;
    int p4 = (int)(idx % (G3 / 4));
    size_t tb = idx / (G3 / 4);
    int b = (int)(tb % BATCH);
    int t = (int)(tb / BATCH);
    int p  = p4 * 4;
    int c  = p / 48;
    int pp = p % 48;
    int g  = pp / UPC;
    int u0 = pp % UPC;
    const float* pb = (b == 0) ? px : (b == 1) ? py : (b == 2) ? vx : vy;
    float x0 = __ldg(pb + 0 * T_LEN + t);
    float x1 = __ldg(pb + 1 * T_LEN + t);
    float x2 = __ldg(pb + 2 * T_LEN + t);
    float x3 = __ldg(pb + 3 * T_LEN + t);
    float r[4];
#pragma unroll
    for (int q = 0; q < 4; q++) {
        int j = g * HID + c * UPC + u0 + q;
        r[q] = g_c[j] + g_M[j * 4 + 0] * x0 + g_M[j * 4 + 1] * x1
                      + g_M[j * 4 + 2] * x2 + g_M[j * 4 + 3] * x3;
    }
    float4* dst = reinterpret_cast<float4*>(&g_gix[tb * G3 + p]);
    *dst = make_float4(r[0], r[1], r[2], r[3]);
}

// ---------------- kernel 2: the sequential GRU scan -------------------------
// 4 clusters of 8 CTAs (one per batch chain). CTA c owns hidden units
// [c*16, c*16+16). Gate math replicated across warps 0-7 (lanes 0-15); warp w
// writes the CTA's 16 new h values to peer w via st.async (data + tx fused on
// peer's phase-split mbarrier) — NO cluster fence, NO separate arrive.
__global__ void __cluster_dims__(CLU, 1, 1) __launch_bounds__(SEQ_THREADS, 1)
gru_scan(const float* __restrict__ W_ih, const float* __restrict__ W_hh,
         const float* __restrict__ b_ih, const float* __restrict__ b_hh,
         const int* __restrict__ step_mask, const int* __restrict__ ctx_ptr) {
    __shared__ __align__(16) float h_buf[2][HID];
    __shared__ float rowsum[2][ROWS];
    __shared__ __align__(8) unsigned long long mbar_storage[2];

    const int tid  = threadIdx.x;
    const int c    = (int)ctarank();
    const int b    = blockIdx.x / CLU;
    const int r    = tid >> 2;       // row 0..95
    const int q    = tid & 3;        // quarter 0..3 (32 k's each)
    const int wid  = tid >> 5;       // warp 0..11
    const int lane = tid & 31;
    const int rot  = ((q << 1) | (r & 1)) & 7;   // bank-conflict-free rotation

    // weight rows -> registers
    const int rl   = (r < 48) ? r : (r - 48);
    const int gate = rl / UPC;
    const int u_r  = rl % UPC;
    const int j    = gate * HID + c * UPC + u_r;
    const float* Wsrc = ((r < 48) ? W_ih : W_hh) + (size_t)j * HID + q * 32;
    const float4* Wsrc4 = reinterpret_cast<const float4*>(Wsrc);
    float4 w[8];
#pragma unroll
    for (int s = 0; s < 8; s++) w[s] = __ldg(&Wsrc4[(s + rot) & 7]);

    // init
    if (tid < HID) { h_buf[0][tid] = 0.0f; h_buf[1][tid] = 0.0f; }
    const uint32_t mb_local[2] = { smem_u32(&mbar_storage[0]), smem_u32(&mbar_storage[1]) };
    if (tid == 0) {
        mbar_init(mb_local[0], 1);
        mbar_init(mb_local[1], 1);
        mbar_expect_tx(mb_local[0], STEP_TX);   // pre-arm both phases
        mbar_expect_tx(mb_local[1], STEP_TX);
    }
    __syncthreads();
    cluster_sync_all();   // peers' armed mbarriers + zeroed h visible before any st.async

    int ctx = ctx_ptr[0];
    if (ctx < 1) ctx = 1;

    const bool peer_warp   = (wid < CLU);               // warps 0..7
    const bool gate_thread = peer_warp && (lane < UPC); // lanes 0..15 of those
    const int  u = lane;                                 // unit (gate threads)

    // biases (replicated across the 8 gate warps)
    float bihr = 0.f, bihz = 0.f, bihn = 0.f, bhhr = 0.f, bhhz = 0.f, bhhn = 0.f;
    if (gate_thread) {
        int gj = c * UPC + u;
        bihr = b_ih[gj]; bihz = b_ih[HID + gj]; bihn = b_ih[2 * HID + gj];
        bhhr = b_hh[gj]; bhhz = b_hh[HID + gj]; bhhn = b_hh[2 * HID + gj];
    }

    // remote addresses: warp w -> peer w; lane u's slot in both buffers + barriers
    uint32_t h_rem[2] = {0, 0}, mb_rem[2] = {0, 0};
    if (gate_thread) {
        h_rem[0]  = mapa_u32(smem_u32(&h_buf[0][c * UPC + u]), (uint32_t)wid);
        h_rem[1]  = mapa_u32(smem_u32(&h_buf[1][c * UPC + u]), (uint32_t)wid);
        mb_rem[0] = mapa_u32(mb_local[0], (uint32_t)wid);
        mb_rem[1] = mapa_u32(mb_local[1], (uint32_t)wid);
    }

    // prefetch gix + mask for t=0 (replicated loads hit L1-broadcast)
    float gnr = 0.f, gnz = 0.f, gnn = 0.f; int nmask = 0;
    if (gate_thread) {
        const float* gp = g_gix + ((size_t)0 * BATCH + b) * G3 + c * 48 + u;
        gnr = __ldg(gp); gnz = __ldg(gp + UPC); gnn = __ldg(gp + 2 * UPC);
        nmask = __ldg(step_mask + 0);
    }

    for (int t = 0; t < T_LEN; t++) {
        const int cur = t & 1;
        const int nb  = cur ^ 1;
        float gcr = gnr, gcz = gnz, gcn = gnn; int cmask = nmask;
        if (gate_thread && (t + 1 < T_LEN)) {
            const float* gp = g_gix + ((size_t)(t + 1) * BATCH + b) * G3 + c * 48 + u;
            gnr = __ldg(gp); gnz = __ldg(gp + UPC); gnn = __ldg(gp + 2 * UPC);
            nmask = __ldg(step_mask + t + 1);
        }

        // ---- dot products: this thread's 32-wide slice of its row ----
        const float4* hb4 = reinterpret_cast<const float4*>(&h_buf[cur][q * 32]);
        float acc = 0.0f;
#pragma unroll
        for (int s = 0; s < 8; s++) {
            float4 h4 = hb4[(s + rot) & 7];
            acc += w[s].x * h4.x + w[s].y * h4.y + w[s].z * h4.z + w[s].w * h4.w;
        }
        acc += __shfl_xor_sync(0xffffffffu, acc, 1);
        acc += __shfl_xor_sync(0xffffffffu, acc, 2);
        if (q == 0) rowsum[cur][r] = acc;
        __syncthreads();

        // ---- replicated gate math + fused store/signal to peer `wid` ----
        if (gate_thread) {
            float gihr = rowsum[cur][u]            + bihr;
            float gihz = rowsum[cur][UPC + u]      + bihz;
            float gihn = rowsum[cur][2 * UPC + u]  + bihn;
            float ghr  = rowsum[cur][48 + u]           + bhhr;
            float ghz  = rowsum[cur][48 + UPC + u]     + bhhz;
            float ghn  = rowsum[cur][48 + 2 * UPC + u] + bhhn;
            bool ux = (t < ctx) || (cmask == 0);
            float gr = ux ? gcr : gihr;
            float gz = ux ? gcz : gihz;
            float gn = ux ? gcn : gihn;
            float rr = sigm_fast(gr + ghr);
            float zz = sigm_fast(gz + ghz);
            float nn = tanh_fast(gn + rr * ghn);
            float hold = h_buf[cur][c * UPC + u];
            float hnew = (1.0f - zz) * nn + zz * hold;
            if (wid == 0)
                g_hs[((size_t)t * BATCH + b) * HID + c * UPC + u] = hnew;
            st_async_f32(h_rem[nb], hnew, mb_rem[nb]);   // data + tx in one shot
        }

        // wait for all 8 CTAs' 16 values (512 tx bytes) for buffer nb
        mbar_wait(mb_local[nb], (uint32_t)((t >> 1) & 1));
        // re-arm this barrier's next phase; the NEXT step's __syncthreads orders
        // this before any store that can target that phase (self or peer).
        if (tid == 0) mbar_expect_tx(mb_local[nb], STEP_TX);
    }
}

// ---------------- kernel 3: MLP head ----------------------------------------
__global__ void __launch_bounds__(256) mlp_head(
    const float* __restrict__ W1, const float* __restrict__ b1,
    const float* __restrict__ W2, const float* __restrict__ b2,
    const float* __restrict__ W3, const float* __restrict__ b3,
    float* __restrict__ out) {
    __shared__ float W1s[HID][64];    // transposed: W1s[k][i] = W1[i][k]
    __shared__ float W3s[2][64];
    __shared__ float b1s[64], b2s[64], b3s[2];
    __shared__ float hrow[4][HID];
    __shared__ float y1s[4][64];
    __shared__ float y2s[4][64];

    const int tid = threadIdx.x;
    for (int idx = tid; idx < 64 * HID; idx += 256) {
        int i = idx / HID, k = idx % HID;
        W1s[k][i] = W1[idx];
    }
    if (tid < 128) W3s[tid >> 6][tid & 63] = W3[tid];
    if (tid < 64)  b1s[tid] = b1[tid];
    if (tid < 64)  b2s[tid] = b2[tid];
    if (tid < 2)   b3s[tid] = b3[tid];
    const int g = tid >> 6, i = tid & 63;
    float w2r[64];
#pragma unroll
    for (int k = 0; k < 64; k++) w2r[k] = __ldg(&W2[i * 64 + k]);
    __syncthreads();

    const int total_rows = T_LEN * BATCH;
    for (int m0 = blockIdx.x * 4; m0 < total_rows; m0 += gridDim.x * 4) {
        for (int x = tid; x < 4 * HID; x += 256)
            hrow[x >> 7][x & 127] = g_hs[(size_t)m0 * HID + x];
        __syncthreads();

        float a = b1s[i];
#pragma unroll 16
        for (int k = 0; k < HID; k++) a += W1s[k][i] * hrow[g][k];
        y1s[g][i] = eluf(a);
        __syncthreads();

        float o = b2s[i];
#pragma unroll
        for (int k = 0; k < 64; k++) o += w2r[k] * y1s[g][k];
        y2s[g][i] = eluf(o);
        __syncthreads();

        if (tid < 8) {
            int gg = tid >> 1, oo = tid & 1;
            int m = m0 + gg;
            float s = b3s[oo];
#pragma unroll
            for (int k = 0; k < 64; k++) s += W3s[oo][k] * y2s[gg][k];
            int t = m >> 2, bb = m & 3;
            out[(size_t)oo * total_rows + (size_t)bb * T_LEN + t] = s;
        }
        __syncthreads();
    }
}

// ---------------- launch -----------------------------------------------------
extern "C" void kernel_launch(void* const* d_in, const int* in_sizes, int n_in,
                              void* d_out, int out_size) {
    const float* px      = (const float*)d_in[0];
    const float* py      = (const float*)d_in[1];
    const float* vx      = (const float*)d_in[2];
    const float* vy      = (const float*)d_in[3];
    const float* W_embed = (const float*)d_in[4];
    const float* b_embed = (const float*)d_in[5];
    const float* W_ih    = (const float*)d_in[6];
    const float* W_hh    = (const float*)d_in[7];
    const float* b_ih    = (const float*)d_in[8];
    const float* b_hh    = (const float*)d_in[9];
    const float* W1      = (const float*)d_in[10];
    const float* b1      = (const float*)d_in[11];
    const float* W2      = (const float*)d_in[12];
    const float* b2      = (const float*)d_in[13];
    const float* W3      = (const float*)d_in[14];
    const float* b3      = (const float*)d_in[15];
    const int*   smask   = (const int*)d_in[16];
    const int*   ctx     = (const int*)d_in[17];

    precompute_Mc<<<1, G3>>>(W_embed, b_embed, W_ih, b_ih);

    const size_t quads = (size_t)T_LEN * BATCH * (G3 / 4);
    fill_gix<<<(unsigned)((quads + 255) / 256), 256>>>(px, py, vx, vy);

    gru_scan<<<BATCH * CLU, SEQ_THREADS>>>(W_ih, W_hh, b_ih, b_hh, smask, ctx);

    mlp_head<<<512, 256>>>(W1, b1, W2, b2, W3, b3, (float*)d_out);
}

// round 13
// speedup vs baseline: 3.5875x; 1.0260x over previous
#include <cuda_runtime.h>
#include <cstdint>

#define T_LEN 16384
#define BATCH 4
#define HID   128
#define G3    384      // 3*HID gate rows per matrix
#define CLU   8        // CTAs per chain (cluster size)
#define UPC   16       // hidden units per CTA
#define ROWS  96       // 48 W_ih rows + 48 W_hh rows per CTA
#define SEQ_THREADS 384
#define STEP_TX (CLU * UPC * 4)   // 512 bytes of h per step per CTA barrier

// ---------------- scratch (static __device__: no allocations allowed) -------
__device__ float g_M[G3 * 4];                          // W_ih @ W_embed  [384,4]
__device__ float g_c[G3];                              // W_ih @ b_embed + b_ih
__device__ float g_gix[(size_t)T_LEN * BATCH * G3];    // precomputed gi for use_x steps
__device__ float g_hs[(size_t)T_LEN * BATCH * HID];    // all hidden states

// ---------------- PTX helpers ----------------------------------------------
__device__ __forceinline__ uint32_t smem_u32(const void* p) {
    uint32_t a;
    asm("{ .reg .u64 t; cvta.to.shared.u64 t, %1; cvt.u32.u64 %0, t; }"
        : "=r"(a) : "l"(p));
    return a;
}
__device__ __forceinline__ uint32_t mapa_u32(uint32_t a, uint32_t rank) {
    uint32_t r;
    asm("mapa.shared::cluster.u32 %0, %1, %2;" : "=r"(r) : "r"(a), "r"(rank));
    return r;
}
__device__ __forceinline__ uint32_t ctarank() {
    uint32_t r; asm("mov.u32 %0, %%cluster_ctarank;" : "=r"(r)); return r;
}
// fused 16-byte data store + tx-completion on the peer's mbarrier (sm_90+)
__device__ __forceinline__ void st_async_v4(uint32_t addr, float v0, float v1,
                                            float v2, float v3, uint32_t mbar) {
    asm volatile(
        "st.async.shared::cluster.mbarrier::complete_tx::bytes.v4.b32 "
        "[%0], {%1, %2, %3, %4}, [%5];"
        :: "r"(addr), "r"(__float_as_uint(v0)), "r"(__float_as_uint(v1)),
           "r"(__float_as_uint(v2)), "r"(__float_as_uint(v3)), "r"(mbar)
        : "memory");
}
__device__ __forceinline__ void mbar_init(uint32_t addr, uint32_t count) {
    asm volatile("mbarrier.init.shared.b64 [%0], %1;" :: "r"(addr), "r"(count) : "memory");
}
__device__ __forceinline__ void mbar_expect_tx(uint32_t addr, uint32_t bytes) {
    asm volatile("mbarrier.arrive.expect_tx.shared.b64 _, [%0], %1;"
                 :: "r"(addr), "r"(bytes) : "memory");
}
__device__ __forceinline__ void mbar_wait(uint32_t mb, uint32_t parity) {
    asm volatile(
        "{\n\t.reg .pred P;\n\t"
        "WLOOP%=:\n\t"
        "mbarrier.try_wait.parity.acquire.cluster.shared::cta.b64 P, [%0], %1, 0x989680;\n\t"
        "@!P bra.uni WLOOP%=;\n\t"
        "}" :: "r"(mb), "r"(parity) : "memory");
}
__device__ __forceinline__ void cluster_sync_all() {
    asm volatile("barrier.cluster.arrive.aligned;" ::: "memory");
    asm volatile("barrier.cluster.wait.aligned;" ::: "memory");
}

__device__ __forceinline__ float sigm_fast(float x) {
    return __fdividef(1.0f, 1.0f + __expf(-x));
}
__device__ __forceinline__ float tanh_fast(float x) {
    float xc = fminf(fmaxf(x, -15.0f), 15.0f);
    float e  = __expf(-2.0f * xc);
    return __fdividef(1.0f - e, 1.0f + e);
}
__device__ __forceinline__ float eluf(float x) { return x > 0.0f ? x : expm1f(x); }

// ---------------- kernel 0: collapse embed+W_ih into [384,4] ----------------
__global__ void precompute_Mc(const float* __restrict__ W_embed,
                              const float* __restrict__ b_embed,
                              const float* __restrict__ W_ih,
                              const float* __restrict__ b_ih) {
    int j = blockIdx.x * blockDim.x + threadIdx.x;
    if (j >= G3) return;
    float m0 = 0.f, m1 = 0.f, m2 = 0.f, m3 = 0.f, cc = b_ih[j];
    for (int k = 0; k < HID; k++) {
        float w = W_ih[j * HID + k];
        m0 += w * W_embed[k * 4 + 0];
        m1 += w * W_embed[k * 4 + 1];
        m2 += w * W_embed[k * 4 + 2];
        m3 += w * W_embed[k * 4 + 3];
        cc += w * b_embed[k];
    }
    g_M[j * 4 + 0] = m0; g_M[j * 4 + 1] = m1;
    g_M[j * 4 + 2] = m2; g_M[j * 4 + 3] = m3;
    g_c[j] = cc;
}

// ---------------- kernel 1: fill gix ----------------------------------------
// Reference: x = stack([px,py,vx,vy],0).transpose(0,2,1) — stacked-tensor axis
// is the model batch; original batch rows are the 4-dim feature vector.
__global__ void fill_gix(const float* __restrict__ px, const float* __restrict__ py,
                         const float* __restrict__ vx, const float* __restrict__ vy) {
    size_t idx = (size_t)blockIdx.x * blockDim.x + threadIdx.x;   // one quad
    const size_t total = (size_t)T_LEN * BATCH * (G3 / 4);
    if (idx >= total) return;
    int p4 = (int)(idx % (G3 / 4));
    size_t tb = idx / (G3 / 4);
    int b = (int)(tb % BATCH);
    int t = (int)(tb / BATCH);
    int p  = p4 * 4;
    int c  = p / 48;
    int pp = p % 48;
    int g  = pp / UPC;
    int u0 = pp % UPC;
    const float* pb = (b == 0) ? px : (b == 1) ? py : (b == 2) ? vx : vy;
    float x0 = __ldg(pb + 0 * T_LEN + t);
    float x1 = __ldg(pb + 1 * T_LEN + t);
    float x2 = __ldg(pb + 2 * T_LEN + t);
    float x3 = __ldg(pb + 3 * T_LEN + t);
    float r[4];
#pragma unroll
    for (int q = 0; q < 4; q++) {
        int j = g * HID + c * UPC + u0 + q;
        r[q] = g_c[j] + g_M[j * 4 + 0] * x0 + g_M[j * 4 + 1] * x1
                      + g_M[j * 4 + 2] * x2 + g_M[j * 4 + 3] * x3;
    }
    float4* dst = reinterpret_cast<float4*>(&g_gix[tb * G3 + p]);
    *dst = make_float4(r[0], r[1], r[2], r[3]);
}

// ---------------- kernel 2: the sequential GRU scan -------------------------
// 4 clusters of 8 CTAs (one per batch chain). CTA c owns hidden units
// [c*16, c*16+16). Gate math replicated across warps 0-7 (lanes 0-15); warp w
// shuffle-gathers its 16 h values into 4 lanes and sends FOUR st.async.v4
// (16B each) to peer w — 32 remote ops / 32 tx-events per barrier per step
// (was 128 scalar). No fence, no separate arrive.
__global__ void __cluster_dims__(CLU, 1, 1) __launch_bounds__(SEQ_THREADS, 1)
gru_scan(const float* __restrict__ W_ih, const float* __restrict__ W_hh,
         const float* __restrict__ b_ih, const float* __restrict__ b_hh,
         const int* __restrict__ step_mask, const int* __restrict__ ctx_ptr) {
    __shared__ __align__(16) float h_buf[2][HID];
    __shared__ float rowsum[2][ROWS];
    __shared__ __align__(8) unsigned long long mbar_storage[2];

    const int tid  = threadIdx.x;
    const int c    = (int)ctarank();
    const int b    = blockIdx.x / CLU;
    const int r    = tid >> 2;       // row 0..95
    const int q    = tid & 3;        // quarter 0..3 (32 k's each)
    const int wid  = tid >> 5;       // warp 0..11
    const int lane = tid & 31;
    const int rot  = ((q << 1) | (r & 1)) & 7;   // bank-conflict-free rotation

    // weight rows -> registers
    const int rl   = (r < 48) ? r : (r - 48);
    const int gate = rl / UPC;
    const int u_r  = rl % UPC;
    const int j    = gate * HID + c * UPC + u_r;
    const float* Wsrc = ((r < 48) ? W_ih : W_hh) + (size_t)j * HID + q * 32;
    const float4* Wsrc4 = reinterpret_cast<const float4*>(Wsrc);
    float4 w[8];
#pragma unroll
    for (int s = 0; s < 8; s++) w[s] = __ldg(&Wsrc4[(s + rot) & 7]);

    // init
    if (tid < HID) { h_buf[0][tid] = 0.0f; h_buf[1][tid] = 0.0f; }
    const uint32_t mb_local[2] = { smem_u32(&mbar_storage[0]), smem_u32(&mbar_storage[1]) };
    if (tid == 0) {
        mbar_init(mb_local[0], 1);
        mbar_init(mb_local[1], 1);
        mbar_expect_tx(mb_local[0], STEP_TX);   // pre-arm both phases
        mbar_expect_tx(mb_local[1], STEP_TX);
    }
    __syncthreads();
    cluster_sync_all();   // peers' armed mbarriers + zeroed h visible before any st.async

    int ctx = ctx_ptr[0];
    if (ctx < 1) ctx = 1;

    const bool peer_warp   = (wid < CLU);               // warps 0..7
    const bool gate_thread = peer_warp && (lane < UPC); // lanes 0..15 of those
    const int  u = lane;                                 // unit (gate threads)

    // biases (replicated across the 8 gate warps)
    float bihr = 0.f, bihz = 0.f, bihn = 0.f, bhhr = 0.f, bhhz = 0.f, bhhn = 0.f;
    if (gate_thread) {
        int gj = c * UPC + u;
        bihr = b_ih[gj]; bihz = b_ih[HID + gj]; bihn = b_ih[2 * HID + gj];
        bhhr = b_hh[gj]; bhhz = b_hh[HID + gj]; bhhn = b_hh[2 * HID + gj];
    }

    // remote addresses: warp w -> peer w; lanes 0-3 own 16B chunk (4*lane..4*lane+3)
    uint32_t h_rem[2] = {0, 0}, mb_rem[2] = {0, 0};
    if (gate_thread) {
        int chunk = (lane & 3) * 4;
        h_rem[0]  = mapa_u32(smem_u32(&h_buf[0][c * UPC + chunk]), (uint32_t)wid);
        h_rem[1]  = mapa_u32(smem_u32(&h_buf[1][c * UPC + chunk]), (uint32_t)wid);
        mb_rem[0] = mapa_u32(mb_local[0], (uint32_t)wid);
        mb_rem[1] = mapa_u32(mb_local[1], (uint32_t)wid);
    }

    // prefetch gix + mask for t=0 (replicated loads hit L1-broadcast)
    float gnr = 0.f, gnz = 0.f, gnn = 0.f; int nmask = 0;
    if (gate_thread) {
        const float* gp = g_gix + ((size_t)0 * BATCH + b) * G3 + c * 48 + u;
        gnr = __ldg(gp); gnz = __ldg(gp + UPC); gnn = __ldg(gp + 2 * UPC);
        nmask = __ldg(step_mask + 0);
    }

    for (int t = 0; t < T_LEN; t++) {
        const int cur = t & 1;
        const int nb  = cur ^ 1;
        float gcr = gnr, gcz = gnz, gcn = gnn; int cmask = nmask;
        if (gate_thread && (t + 1 < T_LEN)) {
            const float* gp = g_gix + ((size_t)(t + 1) * BATCH + b) * G3 + c * 48 + u;
            gnr = __ldg(gp); gnz = __ldg(gp + UPC); gnn = __ldg(gp + 2 * UPC);
            nmask = __ldg(step_mask + t + 1);
        }

        // ---- dot products: this thread's 32-wide slice of its row ----
        const float4* hb4 = reinterpret_cast<const float4*>(&h_buf[cur][q * 32]);
        float acc = 0.0f;
#pragma unroll
        for (int s = 0; s < 8; s++) {
            float4 h4 = hb4[(s + rot) & 7];
            acc += w[s].x * h4.x + w[s].y * h4.y + w[s].z * h4.z + w[s].w * h4.w;
        }
        acc += __shfl_xor_sync(0xffffffffu, acc, 1);
        acc += __shfl_xor_sync(0xffffffffu, acc, 2);
        if (q == 0) rowsum[cur][r] = acc;
        __syncthreads();

        // ---- replicated gate math + packed store/signal to peer `wid` ----
        if (gate_thread) {
            float gihr = rowsum[cur][u]            + bihr;
            float gihz = rowsum[cur][UPC + u]      + bihz;
            float gihn = rowsum[cur][2 * UPC + u]  + bihn;
            float ghr  = rowsum[cur][48 + u]           + bhhr;
            float ghz  = rowsum[cur][48 + UPC + u]     + bhhz;
            float ghn  = rowsum[cur][48 + 2 * UPC + u] + bhhn;
            bool ux = (t < ctx) || (cmask == 0);
            float gr = ux ? gcr : gihr;
            float gz = ux ? gcz : gihz;
            float gn = ux ? gcn : gihn;
            float rr = sigm_fast(gr + ghr);
            float zz = sigm_fast(gz + ghz);
            float nn = tanh_fast(gn + rr * ghn);
            float hold = h_buf[cur][c * UPC + u];
            float hnew = (1.0f - zz) * nn + zz * hold;

            // gather units 4k..4k+3 into lane (k = lane&3); lanes 0-3 get real chunks
            const int base = (lane & 3) << 2;
            float v0 = __shfl_sync(0x0000ffffu, hnew, base + 0);
            float v1 = __shfl_sync(0x0000ffffu, hnew, base + 1);
            float v2 = __shfl_sync(0x0000ffffu, hnew, base + 2);
            float v3 = __shfl_sync(0x0000ffffu, hnew, base + 3);
            if (lane < 4) {
                if (wid == 0) {
                    float4* hp = reinterpret_cast<float4*>(
                        &g_hs[((size_t)t * BATCH + b) * HID + c * UPC + base]);
                    *hp = make_float4(v0, v1, v2, v3);
                }
                st_async_v4(h_rem[nb], v0, v1, v2, v3, mb_rem[nb]);
            }
        }

        // wait for all 8 CTAs' 16 values (512 tx bytes) for buffer nb
        mbar_wait(mb_local[nb], (uint32_t)((t >> 1) & 1));
        // re-arm this barrier's next phase; the NEXT step's __syncthreads orders
        // this before any store that can target that phase (self or peer).
        if (tid == 0) mbar_expect_tx(mb_local[nb], STEP_TX);
    }
}

// ---------------- kernel 3: MLP head ----------------------------------------
__global__ void __launch_bounds__(256) mlp_head(
    const float* __restrict__ W1, const float* __restrict__ b1,
    const float* __restrict__ W2, const float* __restrict__ b2,
    const float* __restrict__ W3, const float* __restrict__ b3,
    float* __restrict__ out) {
    __shared__ float W1s[HID][64];    // transposed: W1s[k][i] = W1[i][k]
    __shared__ float W3s[2][64];
    __shared__ float b1s[64], b2s[64], b3s[2];
    __shared__ float hrow[4][HID];
    __shared__ float y1s[4][64];
    __shared__ float y2s[4][64];

    const int tid = threadIdx.x;
    for (int idx = tid; idx < 64 * HID; idx += 256) {
        int i = idx / HID, k = idx % HID;
        W1s[k][i] = W1[idx];
    }
    if (tid < 128) W3s[tid >> 6][tid & 63] = W3[tid];
    if (tid < 64)  b1s[tid] = b1[tid];
    if (tid < 64)  b2s[tid] = b2[tid];
    if (tid < 2)   b3s[tid] = b3[tid];
    const int g = tid >> 6, i = tid & 63;
    float w2r[64];
#pragma unroll
    for (int k = 0; k < 64; k++) w2r[k] = __ldg(&W2[i * 64 + k]);
    __syncthreads();

    const int total_rows = T_LEN * BATCH;
    for (int m0 = blockIdx.x * 4; m0 < total_rows; m0 += gridDim.x * 4) {
        for (int x = tid; x < 4 * HID; x += 256)
            hrow[x >> 7][x & 127] = g_hs[(size_t)m0 * HID + x];
        __syncthreads();

        float a = b1s[i];
#pragma unroll 16
        for (int k = 0; k < HID; k++) a += W1s[k][i] * hrow[g][k];
        y1s[g][i] = eluf(a);
        __syncthreads();

        float o = b2s[i];
#pragma unroll
        for (int k = 0; k < 64; k++) o += w2r[k] * y1s[g][k];
        y2s[g][i] = eluf(o);
        __syncthreads();

        if (tid < 8) {
            int gg = tid >> 1, oo = tid & 1;
            int m = m0 + gg;
            float s = b3s[oo];
#pragma unroll
            for (int k = 0; k < 64; k++) s += W3s[oo][k] * y2s[gg][k];
            int t = m >> 2, bb = m & 3;
            out[(size_t)oo * total_rows + (size_t)bb * T_LEN + t] = s;
        }
        __syncthreads();
    }
}

// ---------------- launch -----------------------------------------------------
extern "C" void kernel_launch(void* const* d_in, const int* in_sizes, int n_in,
                              void* d_out, int out_size) {
    const float* px      = (const float*)d_in[0];
    const float* py      = (const float*)d_in[1];
    const float* vx      = (const float*)d_in[2];
    const float* vy      = (const float*)d_in[3];
    const float* W_embed = (const float*)d_in[4];
    const float* b_embed = (const float*)d_in[5];
    const float* W_ih    = (const float*)d_in[6];
    const float* W_hh    = (const float*)d_in[7];
    const float* b_ih    = (const float*)d_in[8];
    const float* b_hh    = (const float*)d_in[9];
    const float* W1      = (const float*)d_in[10];
    const float* b1      = (const float*)d_in[11];
    const float* W2      = (const float*)d_in[12];
    const float* b2      = (const float*)d_in[13];
    const float* W3      = (const float*)d_in[14];
    const float* b3      = (const float*)d_in[15];
    const int*   smask   = (const int*)d_in[16];
    const int*   ctx     = (const int*)d_in[17];

    precompute_Mc<<<1, G3>>>(W_embed, b_embed, W_ih, b_ih);

    const size_t quads = (size_t)T_LEN * BATCH * (G3 / 4);
    fill_gix<<<(unsigned)((quads + 255) / 256), 256>>>(px, py, vx, vy);

    gru_scan<<<BATCH * CLU, SEQ_THREADS>>>(W_ih, W_hh, b_ih, b_hh, smask, ctx);

    mlp_head<<<1024, 256>>>(W1, b1, W2, b2, W3, b3, (float*)d_out);
}

// round 15
// speedup vs baseline: 3.9224x; 1.0934x over previous
#include <cuda_runtime.h>
#include <cstdint>

#define T_LEN 16384
#define BATCH 4
#define HID   128
#define G3    384      // 3*HID gate rows per matrix
#define CLU   8        // CTAs per chain (cluster size)
#define UPC   16       // hidden units per CTA
#define ROWS  96       // 48 W_ih rows + 48 W_hh rows per CTA
#define SEQ_THREADS 384
#define QTX   128      // tx bytes per quarter barrier per step (2 peers * 64B)

// ---------------- scratch (static __device__: no allocations allowed) -------
__device__ float g_M[G3 * 4];                          // W_ih @ W_embed  [384,4]
__device__ float g_c[G3];                              // W_ih @ b_embed + b_ih
__device__ float g_gix[(size_t)T_LEN * BATCH * G3];    // precomputed gi for use_x steps
__device__ float g_hs[(size_t)T_LEN * BATCH * HID];    // all hidden states

// ---------------- PTX helpers ----------------------------------------------
__device__ __forceinline__ uint32_t smem_u32(const void* p) {
    uint32_t a;
    asm("{ .reg .u64 t; cvta.to.shared.u64 t, %1; cvt.u32.u64 %0, t; }"
        : "=r"(a) : "l"(p));
    return a;
}
__device__ __forceinline__ uint32_t mapa_u32(uint32_t a, uint32_t rank) {
    uint32_t r;
    asm("mapa.shared::cluster.u32 %0, %1, %2;" : "=r"(r) : "r"(a), "r"(rank));
    return r;
}
__device__ __forceinline__ uint32_t ctarank() {
    uint32_t r; asm("mov.u32 %0, %%cluster_ctarank;" : "=r"(r)); return r;
}
// fused 16-byte data store + tx-completion on the peer's mbarrier (sm_90+)
__device__ __forceinline__ void st_async_v4(uint32_t addr, float v0, float v1,
                                            float v2, float v3, uint32_t mbar) {
    asm volatile(
        "st.async.shared::cluster.mbarrier::complete_tx::bytes.v4.b32 "
        "[%0], {%1, %2, %3, %4}, [%5];"
        :: "r"(addr), "r"(__float_as_uint(v0)), "r"(__float_as_uint(v1)),
           "r"(__float_as_uint(v2)), "r"(__float_as_uint(v3)), "r"(mbar)
        : "memory");
}
__device__ __forceinline__ void mbar_init(uint32_t addr, uint32_t count) {
    asm volatile("mbarrier.init.shared.b64 [%0], %1;" :: "r"(addr), "r"(count) : "memory");
}
__device__ __forceinline__ void mbar_expect_tx(uint32_t addr, uint32_t bytes) {
    asm volatile("mbarrier.arrive.expect_tx.shared.b64 _, [%0], %1;"
                 :: "r"(addr), "r"(bytes) : "memory");
}
__device__ __forceinline__ void mbar_wait(uint32_t mb, uint32_t parity) {
    asm volatile(
        "{\n\t.reg .pred P;\n\t"
        "WLOOP%=:\n\t"
        "mbarrier.try_wait.parity.acquire.cluster.shared::cta.b64 P, [%0], %1, 0x989680;\n\t"
        "@!P bra.uni WLOOP%=;\n\t"
        "}" :: "r"(mb), "r"(parity) : "memory");
}
__device__ __forceinline__ void cluster_sync_all() {
    asm volatile("barrier.cluster.arrive.aligned;" ::: "memory");
    asm volatile("barrier.cluster.wait.aligned;" ::: "memory");
}

__device__ __forceinline__ float sigm_fast(float x) {
    return __fdividef(1.0f, 1.0f + __expf(-x));
}
__device__ __forceinline__ float tanh_fast(float x) {
    float xc = fminf(fmaxf(x, -15.0f), 15.0f);
    float e  = __expf(-2.0f * xc);
    return __fdividef(1.0f - e, 1.0f + e);
}
__device__ __forceinline__ float eluf(float x) { return x > 0.0f ? x : expm1f(x); }

// ---------------- kernel 0: collapse embed+W_ih into [384,4] ----------------
__global__ void precompute_Mc(const float* __restrict__ W_embed,
                              const float* __restrict__ b_embed,
                              const float* __restrict__ W_ih,
                              const float* __restrict__ b_ih) {
    int j = blockIdx.x * blockDim.x + threadIdx.x;
    if (j >= G3) return;
    float m0 = 0.f, m1 = 0.f, m2 = 0.f, m3 = 0.f, cc = b_ih[j];
    for (int k = 0; k < HID; k++) {
        float w = W_ih[j * HID + k];
        m0 += w * W_embed[k * 4 + 0];
        m1 += w * W_embed[k * 4 + 1];
        m2 += w * W_embed[k * 4 + 2];
        m3 += w * W_embed[k * 4 + 3];
        cc += w * b_embed[k];
    }
    g_M[j * 4 + 0] = m0; g_M[j * 4 + 1] = m1;
    g_M[j * 4 + 2] = m2; g_M[j * 4 + 3] = m3;
    g_c[j] = cc;
}

// ---------------- kernel 1: fill gix ----------------------------------------
// Reference: x = stack([px,py,vx,vy],0).transpose(0,2,1) — stacked-tensor axis
// is the model batch; original batch rows are the 4-dim feature vector.
__global__ void fill_gix(const float* __restrict__ px, const float* __restrict__ py,
                         const float* __restrict__ vx, const float* __restrict__ vy) {
    size_t idx = (size_t)blockIdx.x * blockDim.x + threadIdx.x;   // one quad
    const size_t total = (size_t)T_LEN * BATCH * (G3 / 4);
    if (idx >= total) return;
    int p4 = (int)(idx % (G3 / 4));
    size_t tb = idx / (G3 / 4);
    int b = (int)(tb % BATCH);
    int t = (int)(tb / BATCH);
    int p  = p4 * 4;
    int c  = p / 48;
    int pp = p % 48;
    int g  = pp / UPC;
    int u0 = pp % UPC;
    const float* pb = (b == 0) ? px : (b == 1) ? py : (b == 2) ? vx : vy;
    float x0 = __ldg(pb + 0 * T_LEN + t);
    float x1 = __ldg(pb + 1 * T_LEN + t);
    float x2 = __ldg(pb + 2 * T_LEN + t);
    float x3 = __ldg(pb + 3 * T_LEN + t);
    float r[4];
#pragma unroll
    for (int q = 0; q < 4; q++) {
        int j = g * HID + c * UPC + u0 + q;
        r[q] = g_c[j] + g_M[j * 4 + 0] * x0 + g_M[j * 4 + 1] * x1
                      + g_M[j * 4 + 2] * x2 + g_M[j * 4 + 3] * x3;
    }
    float4* dst = reinterpret_cast<float4*>(&g_gix[tb * G3 + p]);
    *dst = make_float4(r[0], r[1], r[2], r[3]);
}

// ---------------- kernel 2: the sequential GRU scan -------------------------
// 4 clusters of 8 CTAs (one per batch chain). CTA c owns hidden units
// [c*16, c*16+16).
// Per-QUARTER split barriers: mb[buf][qd] guards h_buf[buf][qd*32..qd*32+31],
// fed by peers 2qd, 2qd+1 (128 tx bytes). Dot warp w (quarter w&3, rows
// 32*(w>>2)+lane) waits only its own quarter — late peers overlap with dots
// on early quarters instead of stalling the whole CTA.
__global__ void __cluster_dims__(CLU, 1, 1) __launch_bounds__(SEQ_THREADS, 1)
gru_scan(const float* __restrict__ W_ih, const float* __restrict__ W_hh,
         const float* __restrict__ b_ih, const float* __restrict__ b_hh,
         const int* __restrict__ step_mask, const int* __restrict__ ctx_ptr) {
    __shared__ __align__(16) float h_buf[2][HID];
    __shared__ __align__(16) float rps[2][ROWS][4];   // per-quarter row partials
    __shared__ __align__(8) unsigned long long mbar_st[2][4];

    const int tid  = threadIdx.x;
    const int c    = (int)ctarank();
    const int b    = blockIdx.x / CLU;
    const int wid  = tid >> 5;       // warp 0..11
    const int lane = tid & 31;
    const int qd   = wid & 3;        // this warp's h quarter (0..3)
    const int row  = ((wid >> 2) << 5) + lane;   // row 0..95 (one full row slice)

    // weight row -> registers: rows 0..47 = W_ih (gate*16+u), 48..95 = W_hh
    const int rl   = (row < 48) ? row : (row - 48);
    const int gate = rl / UPC;
    const int u_r  = rl % UPC;
    const int j    = gate * HID + c * UPC + u_r;
    const float* Wsrc = ((row < 48) ? W_ih : W_hh) + (size_t)j * HID + qd * 32;
    const float4* Wsrc4 = reinterpret_cast<const float4*>(Wsrc);
    float4 w[8];
#pragma unroll
    for (int s = 0; s < 8; s++) w[s] = __ldg(&Wsrc4[s]);

    // init
    if (tid < HID) { h_buf[0][tid] = 0.0f; h_buf[1][tid] = 0.0f; }
    uint32_t mb_local[2][4];
#pragma unroll
    for (int bb = 0; bb < 2; bb++)
#pragma unroll
        for (int qq = 0; qq < 4; qq++)
            mb_local[bb][qq] = smem_u32(&mbar_st[bb][qq]);
    if (tid == 0) {
#pragma unroll
        for (int bb = 0; bb < 2; bb++)
#pragma unroll
            for (int qq = 0; qq < 4; qq++)
                mbar_init(mb_local[bb][qq], 1);
        // arm only buffer-1 barriers: they receive step-0's sends.
        // buffer-0 barriers are armed in-loop at t=0 (post-bar).
#pragma unroll
        for (int qq = 0; qq < 4; qq++)
            mbar_expect_tx(mb_local[1][qq], QTX);
    }
    __syncthreads();
    cluster_sync_all();   // peers' armed mbarriers + zeroed h visible before any st.async

    int ctx = ctx_ptr[0];
    if (ctx < 1) ctx = 1;

    const bool peer_warp   = (wid < CLU);               // warps 0..7 (one per peer)
    const bool gate_thread = peer_warp && (lane < UPC); // lanes 0..15 of those
    const int  u = lane;                                 // unit (gate threads)
    const int  myq = c >> 1;                             // quarter my units occupy

    // biases (replicated across the 8 gate warps)
    float bihr = 0.f, bihz = 0.f, bihn = 0.f, bhhr = 0.f, bhhz = 0.f, bhhn = 0.f;
    if (gate_thread) {
        int gj = c * UPC + u;
        bihr = b_ih[gj]; bihz = b_ih[HID + gj]; bihn = b_ih[2 * HID + gj];
        bhhr = b_hh[gj]; bhhz = b_hh[HID + gj]; bhhn = b_hh[2 * HID + gj];
    }

    // remote addresses: warp w -> peer w; lanes 0-3 each own one 16B chunk
    uint32_t h_rem[2] = {0, 0}, mb_rem[2] = {0, 0};
    if (gate_thread) {
        int chunk = (lane & 3) * 4;
        h_rem[0]  = mapa_u32(smem_u32(&h_buf[0][c * UPC + chunk]), (uint32_t)wid);
        h_rem[1]  = mapa_u32(smem_u32(&h_buf[1][c * UPC + chunk]), (uint32_t)wid);
        mb_rem[0] = mapa_u32(mb_local[0][myq], (uint32_t)wid);
        mb_rem[1] = mapa_u32(mb_local[1][myq], (uint32_t)wid);
    }

    // prefetch gix + mask for t=0 (replicated loads hit L1-broadcast)
    float gnr = 0.f, gnz = 0.f, gnn = 0.f; int nmask = 0;
    if (gate_thread) {
        const float* gp = g_gix + ((size_t)0 * BATCH + b) * G3 + c * 48 + u;
        gnr = __ldg(gp); gnz = __ldg(gp + UPC); gnn = __ldg(gp + 2 * UPC);
        nmask = __ldg(step_mask + 0);
    }

    for (int t = 0; t < T_LEN; t++) {
        const int cur = t & 1;
        const int nb  = cur ^ 1;
        float gcr = gnr, gcz = gnz, gcn = gnn; int cmask = nmask;
        if (gate_thread && (t + 1 < T_LEN)) {
            const float* gp = g_gix + ((size_t)(t + 1) * BATCH + b) * G3 + c * 48 + u;
            gnr = __ldg(gp); gnz = __ldg(gp + UPC); gnn = __ldg(gp + 2 * UPC);
            nmask = __ldg(step_mask + t + 1);
        }

        // ---- wait ONLY this warp's quarter, then its 32-wide dot slices ----
        if (t > 0)
            mbar_wait(mb_local[cur][qd], (uint32_t)(((t - 1) >> 1) & 1));

        const float4* hb4 = reinterpret_cast<const float4*>(&h_buf[cur][qd * 32]);
        float acc = 0.0f;
#pragma unroll
        for (int s = 0; s < 8; s++) {
            float4 h4 = hb4[s];   // warp-uniform address: smem broadcast
            acc += w[s].x * h4.x + w[s].y * h4.y + w[s].z * h4.z + w[s].w * h4.w;
        }
        rps[cur][row][qd] = acc;
        __syncthreads();

        // re-arm buffer-cur barriers for their next fill (step t+1's sends);
        // safe: all waits on mb[cur] happened before this bar, and the earliest
        // adversarial arrival is a full peer-step away.
        if (wid == 11 && lane < 4) mbar_expect_tx(mb_local[cur][lane], QTX);

        // ---- replicated gate math (warps 0-7) + packed store/signal ----
        if (gate_thread) {
            const float4* r4 = reinterpret_cast<const float4*>(rps[cur]);
            float4 p0 = r4[u];            // ih r row
            float4 p1 = r4[UPC + u];      // ih z row
            float4 p2 = r4[2 * UPC + u];  // ih n row
            float4 p3 = r4[48 + u];           // hh r row
            float4 p4 = r4[48 + UPC + u];     // hh z row
            float4 p5 = r4[48 + 2 * UPC + u]; // hh n row
            float gihr = (p0.x + p0.y) + (p0.z + p0.w) + bihr;
            float gihz = (p1.x + p1.y) + (p1.z + p1.w) + bihz;
            float gihn = (p2.x + p2.y) + (p2.z + p2.w) + bihn;
            float ghr  = (p3.x + p3.y) + (p3.z + p3.w) + bhhr;
            float ghz  = (p4.x + p4.y) + (p4.z + p4.w) + bhhz;
            float ghn  = (p5.x + p5.y) + (p5.z + p5.w) + bhhn;
            bool ux = (t < ctx) || (cmask == 0);
            float gr = ux ? gcr : gihr;
            float gz = ux ? gcz : gihz;
            float gn = ux ? gcn : gihn;
            float rr = sigm_fast(gr + ghr);
            float zz = sigm_fast(gz + ghz);
            float nn = tanh_fast(gn + rr * ghn);
            float hold = h_buf[cur][c * UPC + u];
            float hnew = (1.0f - zz) * nn + zz * hold;

            // gather units 4k..4k+3 into lane k (k = lane&3); lanes 0-3 store
            const int base = (lane & 3) << 2;
            float v0 = __shfl_sync(0x0000ffffu, hnew, base + 0);
            float v1 = __shfl_sync(0x0000ffffu, hnew, base + 1);
            float v2 = __shfl_sync(0x0000ffffu, hnew, base + 2);
            float v3 = __shfl_sync(0x0000ffffu, hnew, base + 3);
            if (lane < 4) {
                if (wid == 0) {
                    float4* hp = reinterpret_cast<float4*>(
                        &g_hs[((size_t)t * BATCH + b) * HID + c * UPC + base]);
                    *hp = make_float4(v0, v1, v2, v3);
                }
                st_async_v4(h_rem[nb], v0, v1, v2, v3, mb_rem[nb]);
            }
        }
    }
    // don't exit while peers' last-step st.async into this CTA may be in flight
    cluster_sync_all();
}

// ---------------- kernel 3: MLP head ----------------------------------------
__global__ void __launch_bounds__(256) mlp_head(
    const float* __restrict__ W1, const float* __restrict__ b1,
    const float* __restrict__ W2, const float* __restrict__ b2,
    const float* __restrict__ W3, const float* __restrict__ b3,
    float* __restrict__ out) {
    __shared__ float W1s[HID][64];    // transposed: W1s[k][i] = W1[i][k]
    __shared__ float W3s[2][64];
    __shared__ float b1s[64], b2s[64], b3s[2];
    __shared__ float hrow[4][HID];
    __shared__ float y1s[4][64];
    __shared__ float y2s[4][64];

    const int tid = threadIdx.x;
    for (int idx = tid; idx < 64 * HID; idx += 256) {
        int i = idx / HID, k = idx % HID;
        W1s[k][i] = W1[idx];
    }
    if (tid < 128) W3s[tid >> 6][tid & 63] = W3[tid];
    if (tid < 64)  b1s[tid] = b1[tid];
    if (tid < 64)  b2s[tid] = b2[tid];
    if (tid < 2)   b3s[tid] = b3[tid];
    const int g = tid >> 6, i = tid & 63;
    float w2r[64];
#pragma unroll
    for (int k = 0; k < 64; k++) w2r[k] = __ldg(&W2[i * 64 + k]);
    __syncthreads();

    const int total_rows = T_LEN * BATCH;
    for (int m0 = blockIdx.x * 4; m0 < total_rows; m0 += gridDim.x * 4) {
        for (int x = tid; x < 4 * HID; x += 256)
            hrow[x >> 7][x & 127] = g_hs[(size_t)m0 * HID + x];
        __syncthreads();

        float a = b1s[i];
#pragma unroll 16
        for (int k = 0; k < HID; k++) a += W1s[k][i] * hrow[g][k];
        y1s[g][i] = eluf(a);
        __syncthreads();

        float o = b2s[i];
#pragma unroll
        for (int k = 0; k < 64; k++) o += w2r[k] * y1s[g][k];
        y2s[g][i] = eluf(o);
        __syncthreads();

        if (tid < 8) {
            int gg = tid >> 1, oo = tid & 1;
            int m = m0 + gg;
            float s = b3s[oo];
#pragma unroll
            for (int k = 0; k < 64; k++) s += W3s[oo][k] * y2s[gg][k];
            int t = m >> 2, bb = m & 3;
            out[(size_t)oo * total_rows + (size_t)bb * T_LEN + t] = s;
        }
        __syncthreads();
    }
}

// ---------------- launch -----------------------------------------------------
extern "C" void kernel_launch(void* const* d_in, const int* in_sizes, int n_in,
                              void* d_out, int out_size) {
    const float* px      = (const float*)d_in[0];
    const float* py      = (const float*)d_in[1];
    const float* vx      = (const float*)d_in[2];
    const float* vy      = (const float*)d_in[3];
    const float* W_embed = (const float*)d_in[4];
    const float* b_embed = (const float*)d_in[5];
    const float* W_ih    = (const float*)d_in[6];
    const float* W_hh    = (const float*)d_in[7];
    const float* b_ih    = (const float*)d_in[8];
    const float* b_hh    = (const float*)d_in[9];
    const float* W1      = (const float*)d_in[10];
    const float* b1      = (const float*)d_in[11];
    const float* W2      = (const float*)d_in[12];
    const float* b2      = (const float*)d_in[13];
    const float* W3      = (const float*)d_in[14];
    const float* b3      = (const float*)d_in[15];
    const int*   smask   = (const int*)d_in[16];
    const int*   ctx     = (const int*)d_in[17];

    precompute_Mc<<<1, G3>>>(W_embed, b_embed, W_ih, b_ih);

    const size_t quads = (size_t)T_LEN * BATCH * (G3 / 4);
    fill_gix<<<(unsigned)((quads + 255) / 256), 256>>>(px, py, vx, vy);

    gru_scan<<<BATCH * CLU, SEQ_THREADS>>>(W_ih, W_hh, b_ih, b_hh, smask, ctx);

    mlp_head<<<1024, 256>>>(W1, b1, W2, b2, W3, b3, (float*)d_out);
}

// round 17
// speedup vs baseline: 4.3294x; 1.1038x over previous
#include <cuda_runtime.h>
#include <cstdint>

#define T_LEN 16384
#define BATCH 4
#define HID   128
#define G3    384      // 3*HID gate rows per matrix
#define CLU   8        // CTAs per chain (cluster size)
#define UPC   16       // hidden units per CTA
#define ROWS  96       // 48 W_ih rows + 48 W_hh rows per CTA
#define SEQ_THREADS 384
#define QTX   128      // tx bytes per quarter barrier per step (2 peers * 64B)

// ---------------- scratch (static __device__: no allocations allowed) -------
__device__ float g_M[G3 * 4];                          // W_ih @ W_embed  [384,4]
__device__ float g_c[G3];                              // W_ih @ b_embed + b_ih
__device__ float g_gix[(size_t)T_LEN * BATCH * G3];    // precomputed gi for use_x steps
__device__ float g_hs[(size_t)T_LEN * BATCH * HID];    // all hidden states

// ---------------- PTX helpers ----------------------------------------------
__device__ __forceinline__ uint32_t smem_u32(const void* p) {
    uint32_t a;
    asm("{ .reg .u64 t; cvta.to.shared.u64 t, %1; cvt.u32.u64 %0, t; }"
        : "=r"(a) : "l"(p));
    return a;
}
__device__ __forceinline__ uint32_t mapa_u32(uint32_t a, uint32_t rank) {
    uint32_t r;
    asm("mapa.shared::cluster.u32 %0, %1, %2;" : "=r"(r) : "r"(a), "r"(rank));
    return r;
}
__device__ __forceinline__ uint32_t ctarank() {
    uint32_t r; asm("mov.u32 %0, %%cluster_ctarank;" : "=r"(r)); return r;
}
// fused 16-byte data store + tx-completion on the peer's mbarrier (sm_90+)
__device__ __forceinline__ void st_async_v4(uint32_t addr, float v0, float v1,
                                            float v2, float v3, uint32_t mbar) {
    asm volatile(
        "st.async.shared::cluster.mbarrier::complete_tx::bytes.v4.b32 "
        "[%0], {%1, %2, %3, %4}, [%5];"
        :: "r"(addr), "r"(__float_as_uint(v0)), "r"(__float_as_uint(v1)),
           "r"(__float_as_uint(v2)), "r"(__float_as_uint(v3)), "r"(mbar)
        : "memory");
}
// packed dual-FMA: d(f32x2) += a(f32x2) * b(f32x2)
__device__ __forceinline__ void fma2(unsigned long long& d,
                                     unsigned long long a, unsigned long long b) {
    asm("fma.rn.f32x2 %0, %1, %2, %0;" : "+l"(d) : "l"(a), "l"(b));
}
__device__ __forceinline__ void mbar_init(uint32_t addr, uint32_t count) {
    asm volatile("mbarrier.init.shared.b64 [%0], %1;" :: "r"(addr), "r"(count) : "memory");
}
__device__ __forceinline__ void mbar_expect_tx(uint32_t addr, uint32_t bytes) {
    asm volatile("mbarrier.arrive.expect_tx.shared.b64 _, [%0], %1;"
                 :: "r"(addr), "r"(bytes) : "memory");
}
__device__ __forceinline__ void mbar_wait(uint32_t mb, uint32_t parity) {
    asm volatile(
        "{\n\t.reg .pred P;\n\t"
        "WLOOP%=:\n\t"
        "mbarrier.try_wait.parity.acquire.cluster.shared::cta.b64 P, [%0], %1, 0x989680;\n\t"
        "@!P bra.uni WLOOP%=;\n\t"
        "}" :: "r"(mb), "r"(parity) : "memory");
}
__device__ __forceinline__ void cluster_sync_all() {
    asm volatile("barrier.cluster.arrive.aligned;" ::: "memory");
    asm volatile("barrier.cluster.wait.aligned;" ::: "memory");
}

__device__ __forceinline__ float sigm_fast(float x) {
    return __fdividef(1.0f, 1.0f + __expf(-x));
}
__device__ __forceinline__ float tanh_fast(float x) {
    float xc = fminf(fmaxf(x, -15.0f), 15.0f);
    float e  = __expf(-2.0f * xc);
    return __fdividef(1.0f - e, 1.0f + e);
}
__device__ __forceinline__ float eluf(float x) { return x > 0.0f ? x : expm1f(x); }

// ---------------- kernel 0: collapse embed+W_ih into [384,4] ----------------
__global__ void precompute_Mc(const float* __restrict__ W_embed,
                              const float* __restrict__ b_embed,
                              const float* __restrict__ W_ih,
                              const float* __restrict__ b_ih) {
    int j = blockIdx.x * blockDim.x + threadIdx.x;
    if (j >= G3) return;
    float m0 = 0.f, m1 = 0.f, m2 = 0.f, m3 = 0.f, cc = b_ih[j];
    for (int k = 0; k < HID; k++) {
        float w = W_ih[j * HID + k];
        m0 += w * W_embed[k * 4 + 0];
        m1 += w * W_embed[k * 4 + 1];
        m2 += w * W_embed[k * 4 + 2];
        m3 += w * W_embed[k * 4 + 3];
        cc += w * b_embed[k];
    }
    g_M[j * 4 + 0] = m0; g_M[j * 4 + 1] = m1;
    g_M[j * 4 + 2] = m2; g_M[j * 4 + 3] = m3;
    g_c[j] = cc;
}

// ---------------- kernel 1: fill gix ----------------------------------------
// Reference: x = stack([px,py,vx,vy],0).transpose(0,2,1) — stacked-tensor axis
// is the model batch; original batch rows are the 4-dim feature vector.
__global__ void fill_gix(const float* __restrict__ px, const float* __restrict__ py,
                         const float* __restrict__ vx, const float* __restrict__ vy) {
    size_t idx = (size_t)blockIdx.x * blockDim.x + threadIdx.x;   // one quad
    const size_t total = (size_t)T_LEN * BATCH * (G3 / 4);
    if (idx >= total) return;
    int p4 = (int)(idx % (G3 / 4));
    size_t tb = idx / (G3 / 4);
    int b = (int)(tb % BATCH);
    int t = (int)(tb / BATCH);
    int p  = p4 * 4;
    int c  = p / 48;
    int pp = p % 48;
    int g  = pp / UPC;
    int u0 = pp % UPC;
    const float* pb = (b == 0) ? px : (b == 1) ? py : (b == 2) ? vx : vy;
    float x0 = __ldg(pb + 0 * T_LEN + t);
    float x1 = __ldg(pb + 1 * T_LEN + t);
    float x2 = __ldg(pb + 2 * T_LEN + t);
    float x3 = __ldg(pb + 3 * T_LEN + t);
    float r[4];
#pragma unroll
    for (int q = 0; q < 4; q++) {
        int j = g * HID + c * UPC + u0 + q;
        r[q] = g_c[j] + g_M[j * 4 + 0] * x0 + g_M[j * 4 + 1] * x1
                      + g_M[j * 4 + 2] * x2 + g_M[j * 4 + 3] * x3;
    }
    float4* dst = reinterpret_cast<float4*>(&g_gix[tb * G3 + p]);
    *dst = make_float4(r[0], r[1], r[2], r[3]);
}

// ---------------- kernel 2: the sequential GRU scan -------------------------
// 4 clusters of 8 CTAs (one per batch chain). CTA c owns hidden units
// [c*16, c*16+16).
// Per-QUARTER split barriers: mb[buf][qd] guards h_buf[buf][qd*32..qd*32+31],
// fed by the 2 CTAs whose units live there (128 tx bytes). Dot warp w waits
// only quarter w&3. Gates computed ONCE on warp 0 (lanes 16-31 mirror lanes
// 0-15); all 8 peers × 4 chunks fan out as 32 st.async.v4 from that single
// warp instruction (lane = peer*4 + chunk).
__global__ void __cluster_dims__(CLU, 1, 1) __launch_bounds__(SEQ_THREADS, 1)
gru_scan(const float* __restrict__ W_ih, const float* __restrict__ W_hh,
         const float* __restrict__ b_ih, const float* __restrict__ b_hh,
         const int* __restrict__ step_mask, const int* __restrict__ ctx_ptr) {
    __shared__ __align__(16) float h_buf[2][HID];
    __shared__ __align__(16) float rps[2][ROWS][4];   // per-quarter row partials
    __shared__ __align__(8) unsigned long long mbar_st[2][4];

    const int tid  = threadIdx.x;
    const int c    = (int)ctarank();
    const int b    = blockIdx.x / CLU;
    const int wid  = tid >> 5;       // warp 0..11
    const int lane = tid & 31;
    const int qd   = wid & 3;        // this warp's h quarter (0..3)
    const int row  = ((wid >> 2) << 5) + lane;   // row 0..95

    // weight row -> registers (as 16 packed f32x2): rows 0..47 = W_ih, 48..95 = W_hh
    const int rl   = (row < 48) ? row : (row - 48);
    const int gate = rl / UPC;
    const int u_r  = rl % UPC;
    const int j    = gate * HID + c * UPC + u_r;
    const float* Wsrc = ((row < 48) ? W_ih : W_hh) + (size_t)j * HID + qd * 32;
    const unsigned long long* Wsrc2 =
        reinterpret_cast<const unsigned long long*>(Wsrc);
    unsigned long long w2[16];
#pragma unroll
    for (int s = 0; s < 16; s++) w2[s] = __ldg(&Wsrc2[s]);

    // init
    if (tid < HID) { h_buf[0][tid] = 0.0f; h_buf[1][tid] = 0.0f; }
    uint32_t mb_local[2][4];
#pragma unroll
    for (int bb = 0; bb < 2; bb++)
#pragma unroll
        for (int qq = 0; qq < 4; qq++)
            mb_local[bb][qq] = smem_u32(&mbar_st[bb][qq]);
    if (tid == 0) {
#pragma unroll
        for (int bb = 0; bb < 2; bb++)
#pragma unroll
            for (int qq = 0; qq < 4; qq++)
                mbar_init(mb_local[bb][qq], 1);
        // arm only buffer-1 barriers (they receive step-0's sends);
        // buffer-0 barriers are armed in-loop at t=0 (post-bar).
#pragma unroll
        for (int qq = 0; qq < 4; qq++)
            mbar_expect_tx(mb_local[1][qq], QTX);
    }
    __syncthreads();
    cluster_sync_all();   // peers' armed mbarriers + zeroed h visible before any st.async

    int ctx = ctx_ptr[0];
    if (ctx < 1) ctx = 1;

    const bool gate_warp = (wid == 0);
    const int  u    = lane & 15;     // unit (lanes 16-31 mirror 0-15)
    const int  peer = lane >> 2;     // which peer CTA this lane sends to
    const int  chnk = lane & 3;      // which 16B chunk of my 16 units
    const int  myq  = c >> 1;        // quarter my units occupy on every CTA

    // biases (warp 0 only; mirrored on high lanes)
    float bihr = 0.f, bihz = 0.f, bihn = 0.f, bhhr = 0.f, bhhz = 0.f, bhhn = 0.f;
    if (gate_warp) {
        int gj = c * UPC + u;
        bihr = b_ih[gj]; bihz = b_ih[HID + gj]; bihn = b_ih[2 * HID + gj];
        bhhr = b_hh[gj]; bhhz = b_hh[HID + gj]; bhhn = b_hh[2 * HID + gj];
    }

    // remote addresses: lane (peer, chnk) -> peer's h slot + quarter barrier
    uint32_t h_rem[2] = {0, 0}, mb_rem[2] = {0, 0};
    if (gate_warp) {
        h_rem[0]  = mapa_u32(smem_u32(&h_buf[0][c * UPC + chnk * 4]), (uint32_t)peer);
        h_rem[1]  = mapa_u32(smem_u32(&h_buf[1][c * UPC + chnk * 4]), (uint32_t)peer);
        mb_rem[0] = mapa_u32(mb_local[0][myq], (uint32_t)peer);
        mb_rem[1] = mapa_u32(mb_local[1][myq], (uint32_t)peer);
    }

    // prefetch gix + mask for t=0
    float gnr = 0.f, gnz = 0.f, gnn = 0.f; int nmask = 0;
    if (gate_warp) {
        const float* gp = g_gix + ((size_t)0 * BATCH + b) * G3 + c * 48 + u;
        gnr = __ldg(gp); gnz = __ldg(gp + UPC); gnn = __ldg(gp + 2 * UPC);
        nmask = __ldg(step_mask + 0);
    }

    for (int t = 0; t < T_LEN; t++) {
        const int cur = t & 1;
        const int nb  = cur ^ 1;
        float gcr = gnr, gcz = gnz, gcn = gnn; int cmask = nmask;
        if (gate_warp && (t + 1 < T_LEN)) {
            const float* gp = g_gix + ((size_t)(t + 1) * BATCH + b) * G3 + c * 48 + u;
            gnr = __ldg(gp); gnz = __ldg(gp + UPC); gnn = __ldg(gp + 2 * UPC);
            nmask = __ldg(step_mask + t + 1);
        }

        // ---- wait ONLY this warp's quarter, then packed-f32x2 dot slices ----
        if (t > 0)
            mbar_wait(mb_local[cur][qd], (uint32_t)(((t - 1) >> 1) & 1));

        const unsigned long long* hb2 =
            reinterpret_cast<const unsigned long long*>(&h_buf[cur][qd * 32]);
        unsigned long long a0 = 0ull, a1 = 0ull;   // two f32x2 accumulator chains
#pragma unroll
        for (int s = 0; s < 8; s++) {
            fma2(a0, w2[2 * s + 0], hb2[2 * s + 0]);
            fma2(a1, w2[2 * s + 1], hb2[2 * s + 1]);
        }
        float acc = (__uint_as_float((uint32_t)a0) + __uint_as_float((uint32_t)(a0 >> 32)))
                  + (__uint_as_float((uint32_t)a1) + __uint_as_float((uint32_t)(a1 >> 32)));
        rps[cur][row][qd] = acc;
        __syncthreads();

        // re-arm buffer-cur barriers for their next fill (step t+1's sends)
        if (wid == 11 && lane < 4) mbar_expect_tx(mb_local[cur][lane], QTX);

        // ---- single-warp gate math + 32-lane fused fan-out ----
        if (gate_warp) {
            const float4* r4 = reinterpret_cast<const float4*>(rps[cur]);
            float4 p0 = r4[u];            // ih r row
            float4 p1 = r4[UPC + u];      // ih z row
            float4 p2 = r4[2 * UPC + u];  // ih n row
            float4 p3 = r4[48 + u];           // hh r row
            float4 p4 = r4[48 + UPC + u];     // hh z row
            float4 p5 = r4[48 + 2 * UPC + u]; // hh n row
            float gihr = (p0.x + p0.y) + (p0.z + p0.w) + bihr;
            float gihz = (p1.x + p1.y) + (p1.z + p1.w) + bihz;
            float gihn = (p2.x + p2.y) + (p2.z + p2.w) + bihn;
            float ghr  = (p3.x + p3.y) + (p3.z + p3.w) + bhhr;
            float ghz  = (p4.x + p4.y) + (p4.z + p4.w) + bhhz;
            float ghn  = (p5.x + p5.y) + (p5.z + p5.w) + bhhn;
            bool ux = (t < ctx) || (cmask == 0);
            float gr = ux ? gcr : gihr;
            float gz = ux ? gcz : gihz;
            float gn = ux ? gcn : gihn;
            float rr = sigm_fast(gr + ghr);
            float zz = sigm_fast(gz + ghz);
            float nn = tanh_fast(gn + rr * ghn);
            float hold = h_buf[cur][c * UPC + u];
            float hnew = (1.0f - zz) * nn + zz * hold;

            // gather chunk chnk (units 4*chnk..4*chnk+3) from lanes 0-15
            const int base = chnk << 2;
            float v0 = __shfl_sync(0xffffffffu, hnew, base + 0);
            float v1 = __shfl_sync(0xffffffffu, hnew, base + 1);
            float v2 = __shfl_sync(0xffffffffu, hnew, base + 2);
            float v3 = __shfl_sync(0xffffffffu, hnew, base + 3);
            if (lane < 4) {   // peer group 0 also spills to gmem
                float4* hp = reinterpret_cast<float4*>(
                    &g_hs[((size_t)t * BATCH + b) * HID + c * UPC + (chnk << 2)]);
                *hp = make_float4(v0, v1, v2, v3);
            }
            st_async_v4(h_rem[nb], v0, v1, v2, v3, mb_rem[nb]);  // 32 lanes, 8 peers
        }
    }
    // don't exit while peers' last-step st.async into this CTA may be in flight
    cluster_sync_all();
}

// ---------------- kernel 3: MLP head ----------------------------------------
__global__ void __launch_bounds__(256) mlp_head(
    const float* __restrict__ W1, const float* __restrict__ b1,
    const float* __restrict__ W2, const float* __restrict__ b2,
    const float* __restrict__ W3, const float* __restrict__ b3,
    float* __restrict__ out) {
    __shared__ float W1s[HID][64];    // transposed: W1s[k][i] = W1[i][k]
    __shared__ float W3s[2][64];
    __shared__ float b1s[64], b2s[64], b3s[2];
    __shared__ float hrow[4][HID];
    __shared__ float y1s[4][64];
    __shared__ float y2s[4][64];

    const int tid = threadIdx.x;
    for (int idx = tid; idx < 64 * HID; idx += 256) {
        int i = idx / HID, k = idx % HID;
        W1s[k][i] = W1[idx];
    }
    if (tid < 128) W3s[tid >> 6][tid & 63] = W3[tid];
    if (tid < 64)  b1s[tid] = b1[tid];
    if (tid < 64)  b2s[tid] = b2[tid];
    if (tid < 2)   b3s[tid] = b3[tid];
    const int g = tid >> 6, i = tid & 63;
    float w2r[64];
#pragma unroll
    for (int k = 0; k < 64; k++) w2r[k] = __ldg(&W2[i * 64 + k]);
    __syncthreads();

    const int total_rows = T_LEN * BATCH;
    for (int m0 = blockIdx.x * 4; m0 < total_rows; m0 += gridDim.x * 4) {
        for (int x = tid; x < 4 * HID; x += 256)
            hrow[x >> 7][x & 127] = g_hs[(size_t)m0 * HID + x];
        __syncthreads();

        float a = b1s[i];
#pragma unroll 16
        for (int k = 0; k < HID; k++) a += W1s[k][i] * hrow[g][k];
        y1s[g][i] = eluf(a);
        __syncthreads();

        float o = b2s[i];
#pragma unroll
        for (int k = 0; k < 64; k++) o += w2r[k] * y1s[g][k];
        y2s[g][i] = eluf(o);
        __syncthreads();

        if (tid < 8) {
            int gg = tid >> 1, oo = tid & 1;
            int m = m0 + gg;
            float s = b3s[oo];
#pragma unroll
            for (int k = 0; k < 64; k++) s += W3s[oo][k] * y2s[gg][k];
            int t = m >> 2, bb = m & 3;
            out[(size_t)oo * total_rows + (size_t)bb * T_LEN + t] = s;
        }
        __syncthreads();
    }
}

// ---------------- launch -----------------------------------------------------
extern "C" void kernel_launch(void* const* d_in, const int* in_sizes, int n_in,
                              void* d_out, int out_size) {
    const float* px      = (const float*)d_in[0];
    const float* py      = (const float*)d_in[1];
    const float* vx      = (const float*)d_in[2];
    const float* vy      = (const float*)d_in[3];
    const float* W_embed = (const float*)d_in[4];
    const float* b_embed = (const float*)d_in[5];
    const float* W_ih    = (const float*)d_in[6];
    const float* W_hh    = (const float*)d_in[7];
    const float* b_ih    = (const float*)d_in[8];
    const float* b_hh    = (const float*)d_in[9];
    const float* W1      = (const float*)d_in[10];
    const float* b1      = (const float*)d_in[11];
    const float* W2      = (const float*)d_in[12];
    const float* b2      = (const float*)d_in[13];
    const float* W3      = (const float*)d_in[14];
    const float* b3      = (const float*)d_in[15];
    const int*   smask   = (const int*)d_in[16];
    const int*   ctx     = (const int*)d_in[17];

    precompute_Mc<<<1, G3>>>(W_embed, b_embed, W_ih, b_ih);

    const size_t quads = (size_t)T_LEN * BATCH * (G3 / 4);
    fill_gix<<<(unsigned)((quads + 255) / 256), 256>>>(px, py, vx, vy);

    gru_scan<<<BATCH * CLU, SEQ_THREADS>>>(W_ih, W_hh, b_ih, b_hh, smask, ctx);

    mlp_head<<<1024, 256>>>(W1, b1, W2, b2, W3, b3, (float*)d_out);
}